// round 15
// baseline (speedup 1.0000x reference)
#include <cuda_runtime.h>
#include <cuda_bf16.h>
#include <cstdint>
#include <math.h>

#define N_NODES 100000
#define F_DIM   128
#define E_EDGES 600000
#define G_GRAPHS 1000
#define HDIM    256
#define C2      (2*HDIM)
#define ECAP    96

typedef __nv_bfloat16 bf16;

// ---------------- scratch (static device memory; no allocs) ----------------
__device__ bf16  d_featH[(size_t)N_NODES * 128];
__device__ bf16  d_featL[(size_t)N_NODES * 128];
__device__ bf16  d_TxH [(size_t)N_NODES * 384];   // [Tx0|Tx1|Tx2] hi
__device__ bf16  d_TxL [(size_t)N_NODES * 384];   // [Tx0|Tx1|Tx2] lo
__device__ float d_H3f [(size_t)N_NODES * 256];   // fp32 partial (G_a output)
__device__ bf16  d_H3H [(size_t)N_NODES * 256];
__device__ bf16  d_H3L [(size_t)N_NODES * 256];
__device__ float d_H4  [(size_t)N_NODES * 256];
__device__ float d_deg [N_NODES];
__device__ float d_ew  [E_EDGES];
__device__ int   d_cnt [N_NODES];
__device__ int   d_elist[(size_t)N_NODES * ECAP];
__device__ float d_T2  [G_GRAPHS * HDIM];
__device__ float d_X2  [G_GRAPHS * HDIM];
__device__ float d_hc  [G_GRAPHS * C2];
__device__ float d_mu  [C2];
__device__ float d_rstd[C2];
__device__ float d_zero[256];                     // never written -> stays 0
// bf16 hi/lo transposed weights [N,K]
__device__ bf16 d_W1tH[128*128], d_W1tL[128*128];
__device__ bf16 d_W2tH[128*128], d_W2tL[128*128];
__device__ bf16 d_WcH [256*384], d_WcL [256*384];   // (Wbig@W3)^T
__device__ bf16 d_W4tH[256*256], d_W4tL[256*256];
__device__ bf16 d_Wc2H[256*128], d_Wc2L[256*128];   // (W5@W6)^T
__device__ bf16 d_W8tH[256*128], d_W8tL[256*128];
__device__ bf16 d_W9tH[256*256], d_W9tL[256*256];
__device__ float d_b3c [256];
__device__ float d_bx  [256];
// graph-side activations
__device__ bf16 d_xLxH[G_GRAPHS*128], d_xLxL[G_GRAPHS*128];
__device__ bf16 d_T1H [G_GRAPHS*256], d_T1L [G_GRAPHS*256];

// ---------------- helpers ----------------
__device__ __forceinline__ uint32_t smem_to_u32(const void* p) {
    uint32_t a;
    asm("{ .reg .u64 t; cvta.to.shared.u64 t, %1; cvt.u32.u64 %0, t; }" : "=r"(a) : "l"(p));
    return a;
}
__device__ __forceinline__ void split1(float v, bf16& h, bf16& l) {
    h = __float2bfloat16(v);
    l = __float2bfloat16(v - __bfloat162float(h));
}
__device__ __forceinline__ uint32_t pack2h(float a, float b) {
    __nv_bfloat162 t = __floats2bfloat162_rn(a, b);
    return *reinterpret_cast<uint32_t*>(&t);
}
__device__ __forceinline__ uint32_t pack2l(float a, float b) {
    float ra = a - __bfloat162float(__float2bfloat16(a));
    float rb = b - __bfloat162float(__float2bfloat16(b));
    __nv_bfloat162 t = __floats2bfloat162_rn(ra, rb);
    return *reinterpret_cast<uint32_t*>(&t);
}
__device__ __forceinline__ float2 rec2(uint32_t h, uint32_t l) {
    __nv_bfloat162 hh = *reinterpret_cast<__nv_bfloat162*>(&h);
    __nv_bfloat162 ll = *reinterpret_cast<__nv_bfloat162*>(&l);
    return make_float2(__bfloat162float(hh.x) + __bfloat162float(ll.x),
                       __bfloat162float(hh.y) + __bfloat162float(ll.y));
}

#define LDMX4(r, addr)                                                          \
    asm volatile("ldmatrix.sync.aligned.m8n8.x4.shared.b16 {%0,%1,%2,%3}, [%4];"\
        : "=r"((r)[0]), "=r"((r)[1]), "=r"((r)[2]), "=r"((r)[3]) : "r"(addr))

#define CP16(dst, src, sz)                                                      \
    asm volatile("cp.async.cg.shared.global [%0], [%1], 16, %2;"                \
        :: "r"(dst), "l"(src), "r"(sz))

#define MMA4(d, a, b0v, b1v)                                                    \
    asm("mma.sync.aligned.m16n8k16.row.col.f32.bf16.bf16.f32 "                  \
        "{%0,%1,%2,%3}, {%4,%5,%6,%7}, {%8,%9}, {%0,%1,%2,%3};"                 \
        : "+f"((d)[0]), "+f"((d)[1]), "+f"((d)[2]), "+f"((d)[3])                \
        : "r"((a)[0]), "r"((a)[1]), "r"((a)[2]), "r"((a)[3]), "r"(b0v), "r"(b1v))

// ---------------- GEMM: C = act(A @ Bt^T + Cin + bias), bf16x3 split ---------
__global__ __launch_bounds__(256, 2)
void gemm_bf16x3(const bf16* __restrict__ Ahi, const bf16* __restrict__ Alo, int lda,
                 const bf16* __restrict__ Bhi, const bf16* __restrict__ Blo, int ldb,
                 const float* __restrict__ bias,
                 const float* __restrict__ Cin, int ldcin,
                 float* __restrict__ Cf, int ldcf,
                 bf16* __restrict__ Chi, bf16* __restrict__ Clo, int ldch,
                 int M, int K, int act) {
    extern __shared__ char smem[];
    const uint32_t sbase = smem_to_u32(smem);
    const int tid = threadIdx.x, lane = tid & 31, wid = tid >> 5;
    const int wm = wid >> 2, wn = wid & 3;
    const int bm = blockIdx.y * 128, bn = blockIdx.x * 128;
    const int nch = K >> 5;            // always even

    float acc[4][4][4];
#pragma unroll
    for (int i = 0; i < 4; i++)
#pragma unroll
        for (int j = 0; j < 4; j++)
#pragma unroll
            for (int r = 0; r < 4; r++) acc[i][j][r] = 0.f;

    const int r0 = tid >> 2, ch = tid & 3;
    const int r1 = r0 + 64;
    const uint32_t sz0 = (bm + r0 < M) ? 16u : 0u;
    const uint32_t sz1 = (bm + r1 < M) ? 16u : 0u;
    const char* pA0h = (const char*)(Ahi + (size_t)(bm + r0) * lda + ch * 8);
    const char* pA0l = (const char*)(Alo + (size_t)(bm + r0) * lda + ch * 8);
    const char* pA1h = (const char*)(Ahi + (size_t)(bm + r1) * lda + ch * 8);
    const char* pA1l = (const char*)(Alo + (size_t)(bm + r1) * lda + ch * 8);
    const char* pB0h = (const char*)(Bhi + (size_t)(bn + r0) * ldb + ch * 8);
    const char* pB0l = (const char*)(Blo + (size_t)(bn + r0) * ldb + ch * 8);
    const char* pB1h = (const char*)(Bhi + (size_t)(bn + r1) * ldb + ch * 8);
    const char* pB1l = (const char*)(Blo + (size_t)(bn + r1) * ldb + ch * 8);
    const uint32_t dA0 = sbase + r0 * 80 + ch * 16;
    const uint32_t dA1 = dA0 + 64 * 80;
    const uint32_t dB0 = dA0 + 20480;
    const uint32_t dB1 = dA1 + 20480;

    auto stage_load = [&](int c, uint32_t so) {
        const uint32_t ko = (uint32_t)c * 64u;
        CP16(dA0 + so,         pA0h + ko, sz0);
        CP16(dA0 + so + 10240, pA0l + ko, sz0);
        CP16(dA1 + so,         pA1h + ko, sz1);
        CP16(dA1 + so + 10240, pA1l + ko, sz1);
        CP16(dB0 + so,         pB0h + ko, 16u);
        CP16(dB0 + so + 10240, pB0l + ko, 16u);
        CP16(dB1 + so,         pB1h + ko, 16u);
        CP16(dB1 + so + 10240, pB1l + ko, 16u);
    };

    stage_load(0, 0);
    asm volatile("cp.async.commit_group;");
    stage_load(1, 40960);
    asm volatile("cp.async.commit_group;");

    const int rsub = ((lane >> 3) & 1) * 8 + (lane & 7);
    const uint32_t csel = (uint32_t)((lane >> 4) << 4);
    const uint32_t aBase = sbase + (uint32_t)(wm * 64 + rsub) * 80 + csel;
    const uint32_t bBase = sbase + 20480 + (uint32_t)(wn * 32 + rsub) * 80 + csel;

    auto chunk = [&](int c, uint32_t so) {
        asm volatile("cp.async.wait_group 1;");
        __syncthreads();
#pragma unroll
        for (int kt = 0; kt < 2; kt++) {
            const uint32_t ko = so + (uint32_t)(kt * 32);
            uint32_t bh[2][4], bl[2][4];
#pragma unroll
            for (int np = 0; np < 2; np++) {
                LDMX4(bh[np], bBase + ko + np * 1280);
                LDMX4(bl[np], bBase + ko + np * 1280 + 10240);
            }
#pragma unroll
            for (int i = 0; i < 4; i++) {
                uint32_t ah[4], al[4];
                LDMX4(ah, aBase + ko + i * 1280);
                LDMX4(al, aBase + ko + i * 1280 + 10240);
#pragma unroll
                for (int j = 0; j < 4; j++) {
                    const int np = j >> 1, o = j & 1;
                    MMA4(acc[i][j], ah, bh[np][o], bh[np][2 + o]);
                    MMA4(acc[i][j], ah, bl[np][o], bl[np][2 + o]);
                    MMA4(acc[i][j], al, bh[np][o], bh[np][2 + o]);
                }
            }
        }
        __syncthreads();
        if (c + 2 < nch) stage_load(c + 2, so);
        asm volatile("cp.async.commit_group;");
    };

    for (int c = 0; c < nch; c += 2) {
        chunk(c, 0);
        chunk(c + 1, 40960);
    }

    const int g = lane >> 2, tg = lane & 3;
#pragma unroll
    for (int i = 0; i < 4; i++) {
        const int row0 = bm + wm * 64 + i * 16 + g;
#pragma unroll
        for (int j = 0; j < 4; j++) {
            const int col = bn + wn * 32 + j * 8 + tg * 2;
            const float b0 = bias[col], b1 = bias[col + 1];
#pragma unroll
            for (int h = 0; h < 2; h++) {
                const int row = row0 + h * 8;
                if (row >= M) continue;
                float v0 = acc[i][j][h * 2 + 0] + b0;
                float v1 = acc[i][j][h * 2 + 1] + b1;
                if (Cin) {
                    float2 ci = *reinterpret_cast<const float2*>(&Cin[(size_t)row * ldcin + col]);
                    v0 += ci.x; v1 += ci.y;
                }
                if (act) {
                    v0 = v0 > 0.f ? v0 : 0.01f * v0;
                    v1 = v1 > 0.f ? v1 : 0.01f * v1;
                }
                if (Cf) {
                    float2 fv = make_float2(v0, v1);
                    *reinterpret_cast<float2*>(&Cf[(size_t)row * ldcf + col]) = fv;
                }
                if (Chi) {
                    *reinterpret_cast<uint32_t*>(&Chi[(size_t)row * ldch + col]) = pack2h(v0, v1);
                    *reinterpret_cast<uint32_t*>(&Clo[(size_t)row * ldch + col]) = pack2l(v0, v1);
                }
            }
        }
    }
}

// ---------------- fused W1+W2 GEMM (no fp32 output) --------------------------
__global__ __launch_bounds__(256, 2)
void gemm12(const bf16* __restrict__ fH, const bf16* __restrict__ fL,
            const bf16* __restrict__ W1H, const bf16* __restrict__ W1L,
            const float* __restrict__ b1,
            const bf16* __restrict__ W2H, const bf16* __restrict__ W2L,
            const float* __restrict__ b2,
            bf16* __restrict__ TxH, bf16* __restrict__ TxL,
            int M) {
    extern __shared__ char smem[];
    const uint32_t sbase = smem_to_u32(smem);
    const int tid = threadIdx.x, lane = tid & 31, wid = tid >> 5;
    const int wm = wid >> 2, wn = wid & 3;
    const int bm = blockIdx.x * 128;

    float acc[4][4][4];
#pragma unroll
    for (int i = 0; i < 4; i++)
#pragma unroll
        for (int j = 0; j < 4; j++)
#pragma unroll
            for (int r = 0; r < 4; r++) acc[i][j][r] = 0.f;

    const int r0 = tid >> 2, ch = tid & 3;
    const int r1 = r0 + 64;
    const uint32_t sz0 = (bm + r0 < M) ? 16u : 0u;
    const uint32_t sz1 = (bm + r1 < M) ? 16u : 0u;
    const uint32_t dA0 = sbase + r0 * 80 + ch * 16;
    const uint32_t dA1 = dA0 + 64 * 80;
    const uint32_t dB0 = dA0 + 20480;
    const uint32_t dB1 = dA1 + 20480;

    {
        const char* pA0h = (const char*)(fH + (size_t)(bm + r0) * 128 + ch * 8);
        const char* pA0l = (const char*)(fL + (size_t)(bm + r0) * 128 + ch * 8);
        const char* pA1h = (const char*)(fH + (size_t)(bm + r1) * 128 + ch * 8);
        const char* pA1l = (const char*)(fL + (size_t)(bm + r1) * 128 + ch * 8);
        const char* pB0h = (const char*)(W1H + (size_t)r0 * 128 + ch * 8);
        const char* pB0l = (const char*)(W1L + (size_t)r0 * 128 + ch * 8);
        const char* pB1h = (const char*)(W1H + (size_t)r1 * 128 + ch * 8);
        const char* pB1l = (const char*)(W1L + (size_t)r1 * 128 + ch * 8);

        auto stage_load = [&](int c, uint32_t so) {
            const uint32_t ko = (uint32_t)c * 64u;
            CP16(dA0 + so,         pA0h + ko, sz0);
            CP16(dA0 + so + 10240, pA0l + ko, sz0);
            CP16(dA1 + so,         pA1h + ko, sz1);
            CP16(dA1 + so + 10240, pA1l + ko, sz1);
            CP16(dB0 + so,         pB0h + ko, 16u);
            CP16(dB0 + so + 10240, pB0l + ko, 16u);
            CP16(dB1 + so,         pB1h + ko, 16u);
            CP16(dB1 + so + 10240, pB1l + ko, 16u);
        };

        stage_load(0, 0);
        asm volatile("cp.async.commit_group;");
        stage_load(1, 40960);
        asm volatile("cp.async.commit_group;");

        const int rsub = ((lane >> 3) & 1) * 8 + (lane & 7);
        const uint32_t csel = (uint32_t)((lane >> 4) << 4);
        const uint32_t aBase = sbase + (uint32_t)(wm * 64 + rsub) * 80 + csel;
        const uint32_t bBase = sbase + 20480 + (uint32_t)(wn * 32 + rsub) * 80 + csel;

        auto chunk = [&](int c, uint32_t so) {
            asm volatile("cp.async.wait_group 1;");
            __syncthreads();
#pragma unroll
            for (int kt = 0; kt < 2; kt++) {
                const uint32_t ko = so + (uint32_t)(kt * 32);
                uint32_t bh[2][4], bl[2][4];
#pragma unroll
                for (int np = 0; np < 2; np++) {
                    LDMX4(bh[np], bBase + ko + np * 1280);
                    LDMX4(bl[np], bBase + ko + np * 1280 + 10240);
                }
#pragma unroll
                for (int i = 0; i < 4; i++) {
                    uint32_t ah[4], al[4];
                    LDMX4(ah, aBase + ko + i * 1280);
                    LDMX4(al, aBase + ko + i * 1280 + 10240);
#pragma unroll
                    for (int j = 0; j < 4; j++) {
                        const int np = j >> 1, o = j & 1;
                        MMA4(acc[i][j], ah, bh[np][o], bh[np][2 + o]);
                        MMA4(acc[i][j], ah, bl[np][o], bl[np][2 + o]);
                        MMA4(acc[i][j], al, bh[np][o], bh[np][2 + o]);
                    }
                }
            }
            __syncthreads();
            if (c + 2 < 4) stage_load(c + 2, so);
            asm volatile("cp.async.commit_group;");
        };

        chunk(0, 0);
        chunk(1, 40960);
        chunk(2, 0);
        chunk(3, 40960);
    }

    const int g = lane >> 2, tg = lane & 3;
#pragma unroll
    for (int i = 0; i < 4; i++) {
        const int crow = wm * 64 + i * 16 + g;
#pragma unroll
        for (int j = 0; j < 4; j++) {
            const int col = wn * 32 + j * 8 + tg * 2;
            const float b0 = b1[col], b1v = b1[col + 1];
            const int c2 = col >> 5, kin = col & 31;
            const uint32_t base = sbase + (uint32_t)c2 * 20480 + kin * 2;
#pragma unroll
            for (int h = 0; h < 2; h++) {
                float v0 = acc[i][j][h * 2 + 0] + b0;
                float v1 = acc[i][j][h * 2 + 1] + b1v;
                v0 = v0 > 0.f ? v0 : 0.01f * v0;
                v1 = v1 > 0.f ? v1 : 0.01f * v1;
                const uint32_t a = base + (uint32_t)(crow + h * 8) * 80;
                *reinterpret_cast<uint32_t*>(smem + (a - sbase))         = pack2h(v0, v1);
                *reinterpret_cast<uint32_t*>(smem + (a - sbase) + 10240) = pack2l(v0, v1);
                acc[i][j][h * 2 + 0] = 0.f;
                acc[i][j][h * 2 + 1] = 0.f;
            }
        }
    }
    __syncthreads();

    {
        const char* pW0h = (const char*)(W2H + (size_t)r0 * 128 + ch * 8);
        const char* pW0l = (const char*)(W2L + (size_t)r0 * 128 + ch * 8);
        const char* pW1h = (const char*)(W2H + (size_t)r1 * 128 + ch * 8);
        const char* pW1l = (const char*)(W2L + (size_t)r1 * 128 + ch * 8);
        const uint32_t eB0 = sbase + 81920 + r0 * 80 + ch * 16;
        const uint32_t eB1 = eB0 + 64 * 80;

        const int rsub = ((lane >> 3) & 1) * 8 + (lane & 7);
        const uint32_t csel = (uint32_t)((lane >> 4) << 4);
        const uint32_t aB2 = sbase + (uint32_t)(wm * 64 + rsub) * 80 + csel;
        const uint32_t bB2 = sbase + 81920 + (uint32_t)(wn * 32 + rsub) * 80 + csel;

        for (int c2 = 0; c2 < 4; c2++) {
            const uint32_t ko = (uint32_t)c2 * 64u;
            CP16(eB0,         pW0h + ko, 16u);
            CP16(eB0 + 10240, pW0l + ko, 16u);
            CP16(eB1,         pW1h + ko, 16u);
            CP16(eB1 + 10240, pW1l + ko, 16u);
            asm volatile("cp.async.commit_group;");
            asm volatile("cp.async.wait_group 0;");
            __syncthreads();
            const uint32_t aC = aB2 + (uint32_t)c2 * 20480;
#pragma unroll
            for (int kt = 0; kt < 2; kt++) {
                const uint32_t ko2 = (uint32_t)(kt * 32);
                uint32_t bh[2][4], bl[2][4];
#pragma unroll
                for (int np = 0; np < 2; np++) {
                    LDMX4(bh[np], bB2 + ko2 + np * 1280);
                    LDMX4(bl[np], bB2 + ko2 + np * 1280 + 10240);
                }
#pragma unroll
                for (int i = 0; i < 4; i++) {
                    uint32_t ah[4], al[4];
                    LDMX4(ah, aC + ko2 + i * 1280);
                    LDMX4(al, aC + ko2 + i * 1280 + 10240);
#pragma unroll
                    for (int j = 0; j < 4; j++) {
                        const int np = j >> 1, o = j & 1;
                        MMA4(acc[i][j], ah, bh[np][o], bh[np][2 + o]);
                        MMA4(acc[i][j], ah, bl[np][o], bl[np][2 + o]);
                        MMA4(acc[i][j], al, bh[np][o], bh[np][2 + o]);
                    }
                }
            }
            __syncthreads();
        }
    }

#pragma unroll
    for (int i = 0; i < 4; i++) {
        const int row0 = bm + wm * 64 + i * 16 + g;
#pragma unroll
        for (int j = 0; j < 4; j++) {
            const int col = wn * 32 + j * 8 + tg * 2;
            const float c0 = b2[col], c1 = b2[col + 1];
#pragma unroll
            for (int h = 0; h < 2; h++) {
                const int row = row0 + h * 8;
                if (row >= M) continue;
                float v0 = acc[i][j][h * 2 + 0] + c0;
                float v1 = acc[i][j][h * 2 + 1] + c1;
                v0 = v0 > 0.f ? v0 : 0.01f * v0;
                v1 = v1 > 0.f ? v1 : 0.01f * v1;
                *reinterpret_cast<uint32_t*>(&TxH[(size_t)row * 384 + col]) = pack2h(v0, v1);
                *reinterpret_cast<uint32_t*>(&TxL[(size_t)row * 384 + col]) = pack2l(v0, v1);
            }
        }
    }
}

// ---------------- weight-combination builders ----------------
__global__ void build_wcombo(const float* __restrict__ chebW, const float* __restrict__ W3,
                             const float* __restrict__ chebb, const float* __restrict__ b3,
                             bf16* __restrict__ WcH, bf16* __restrict__ WcL,
                             float* __restrict__ b3c) {
    int c = threadIdx.x;
    if (blockIdx.x == 384) {
        float acc = b3[c];
        for (int n = 0; n < 512; n++) acc += chebb[n] * W3[n * 256 + c];
        b3c[c] = acc;
        return;
    }
    __shared__ float wrow[512];
    int k = blockIdx.x;
    int kk = k >> 7, i = k & 127;
    for (int idx = c; idx < 512; idx += 256) {
        int w = idx >> 7, j = idx & 127;
        wrow[idx] = chebW[(((w * 3) + kk) * 128 + i) * 128 + j];
    }
    __syncthreads();
    float acc = 0.f;
#pragma unroll 8
    for (int j = 0; j < 512; j++) acc += wrow[j] * W3[j * 256 + c];
    bf16 h, l; split1(acc, h, l);
    WcH[c * 384 + k] = h; WcL[c * 384 + k] = l;
}

__global__ void build_wc2(const float* __restrict__ W5, const float* __restrict__ W6,
                          const float* __restrict__ b5, const float* __restrict__ b6,
                          bf16* __restrict__ Wc2H, bf16* __restrict__ Wc2L,
                          float* __restrict__ bx) {
    int c = threadIdx.x;
    if (blockIdx.x == 128) {
        float acc = b6[c];
        for (int j = 0; j < 256; j++) acc += b5[j] * W6[j * 256 + c];
        bx[c] = acc;
        return;
    }
    __shared__ float wrow[256];
    int k = blockIdx.x;
    wrow[c] = W5[k * 256 + c];
    __syncthreads();
    float acc = 0.f;
#pragma unroll 8
    for (int j = 0; j < 256; j++) acc += wrow[j] * W6[j * 256 + c];
    bf16 h, l; split1(acc, h, l);
    Wc2H[c * 128 + k] = h; Wc2L[c * 128 + k] = l;
}

// ---------------- prep / convert kernels ----------------
__global__ void zero_dc(float* deg, int* cnt, int n) {
    int i = blockIdx.x * 256 + threadIdx.x;
    if (i < n) { deg[i] = 0.f; cnt[i] = 0; }
}
__global__ void split_contig(const float* __restrict__ s, bf16* __restrict__ h,
                             bf16* __restrict__ l, int n) {
    int i = blockIdx.x * 256 + threadIdx.x;
    if (i < n) { bf16 hh, ll; split1(s[i], hh, ll); h[i] = hh; l[i] = ll; }
}
__global__ void transpose_w12(const float* __restrict__ W1, bf16* __restrict__ W1tH, bf16* __restrict__ W1tL,
                              const float* __restrict__ W2, bf16* __restrict__ W2tH, bf16* __restrict__ W2tL) {
    int idx = blockIdx.x * 256 + threadIdx.x;
    if (idx >= 32768) return;
    const float* W = (idx < 16384) ? W1 : W2;
    bf16* Th = (idx < 16384) ? W1tH : W2tH;
    bf16* Tl = (idx < 16384) ? W1tL : W2tL;
    int t = idx & 16383;
    int k = t >> 7, n = t & 127;
    bf16 h, l; split1(W[t], h, l);
    Th[n * 128 + k] = h; Tl[n * 128 + k] = l;
}
__global__ void transpose3(const float* __restrict__ W4, bf16* __restrict__ W4tH, bf16* __restrict__ W4tL,
                           const float* __restrict__ W8, bf16* __restrict__ W8tH, bf16* __restrict__ W8tL,
                           const float* __restrict__ W9, bf16* __restrict__ W9tH, bf16* __restrict__ W9tL) {
    int idx = blockIdx.x * 256 + threadIdx.x;
    const float* W; bf16 *Th, *Tl; int K, t;
    if (idx < 65536)       { W = W4; Th = W4tH; Tl = W4tL; K = 256; t = idx; }
    else if (idx < 98304)  { W = W8; Th = W8tH; Tl = W8tL; K = 128; t = idx - 65536; }
    else if (idx < 163840) { W = W9; Th = W9tH; Tl = W9tL; K = 256; t = idx - 98304; }
    else return;
    int k = t / 256, n = t % 256;
    bf16 h, l; split1(W[t], h, l);
    Th[n * K + k] = h; Tl[n * K + k] = l;
}

// ---------------- graph structure ----------------
__global__ void build_graph(const int* __restrict__ src, const int* __restrict__ dst, int e,
                            float* __restrict__ deg, int* __restrict__ cnt,
                            int* __restrict__ elist) {
    int i = blockIdx.x * 256 + threadIdx.x;
    if (i >= e) return;
    atomicAdd(&deg[src[i]], 1.0f);
    int d = dst[i];
    int p = atomicAdd(&cnt[d], 1);
    if (p < ECAP) elist[(size_t)d * ECAP + p] = i;
}
__global__ void ew_kernel(const int* __restrict__ src, const int* __restrict__ dst,
                          const float* __restrict__ deg, float* __restrict__ ew, int e) {
    int i = blockIdx.x * 256 + threadIdx.x;
    if (i >= e) return;
    float ds = rsqrtf(fmaxf(deg[src[i]], 1.f));
    float dv = deg[dst[i]];
    float dd = (dv > 0.f) ? rsqrtf(fmaxf(dv, 1.f)) : 0.f;
    ew[i] = -(ds * dd);
}

// prop #1: Tx1 = P(Tx0)
__global__ void prop_split1(bf16* __restrict__ TxH, bf16* __restrict__ TxL,
                            const float* __restrict__ ew,
                            const int* __restrict__ src, const int* __restrict__ elist,
                            const int* __restrict__ cnt, int n) {
    int v = (blockIdx.x * 256 + threadIdx.x) >> 5;
    int lane = threadIdx.x & 31;
    if (v >= n) return;
    int c = cnt[v];
    if (c > ECAP) c = ECAP;
    float4 acc = make_float4(0.f, 0.f, 0.f, 0.f);
    const int* el = &elist[(size_t)v * ECAP];
    for (int i = 0; i < c; i++) {
        int eid = el[i];
        int s = src[eid];
        float w = ew[eid];
        size_t p = (size_t)s * 384 + lane * 4;
        uint2 h = *reinterpret_cast<const uint2*>(&TxH[p]);
        uint2 l = *reinterpret_cast<const uint2*>(&TxL[p]);
        float2 a = rec2(h.x, l.x), b = rec2(h.y, l.y);
        acc.x += w * a.x; acc.y += w * a.y; acc.z += w * b.x; acc.w += w * b.y;
    }
    size_t o = (size_t)v * 384 + 128 + lane * 4;
    *reinterpret_cast<uint32_t*>(&TxH[o])     = pack2h(acc.x, acc.y);
    *reinterpret_cast<uint32_t*>(&TxH[o + 2]) = pack2h(acc.z, acc.w);
    *reinterpret_cast<uint32_t*>(&TxL[o])     = pack2l(acc.x, acc.y);
    *reinterpret_cast<uint32_t*>(&TxL[o + 2]) = pack2l(acc.z, acc.w);
}

// prop #2: Tx2 = 2*P(Tx1) - Tx0
__global__ void prop_split2(bf16* __restrict__ TxH, bf16* __restrict__ TxL,
                            const float* __restrict__ ew,
                            const int* __restrict__ src, const int* __restrict__ elist,
                            const int* __restrict__ cnt, int n) {
    int v = (blockIdx.x * 256 + threadIdx.x) >> 5;
    int lane = threadIdx.x & 31;
    if (v >= n) return;
    int c = cnt[v];
    if (c > ECAP) c = ECAP;
    float4 acc = make_float4(0.f, 0.f, 0.f, 0.f);
    const int* el = &elist[(size_t)v * ECAP];
    for (int i = 0; i < c; i++) {
        int eid = el[i];
        int s = src[eid];
        float w = ew[eid];
        size_t p = (size_t)s * 384 + 128 + lane * 4;
        uint2 h = *reinterpret_cast<const uint2*>(&TxH[p]);
        uint2 l = *reinterpret_cast<const uint2*>(&TxL[p]);
        float2 a = rec2(h.x, l.x), b = rec2(h.y, l.y);
        acc.x += w * a.x; acc.y += w * a.y; acc.z += w * b.x; acc.w += w * b.y;
    }
    size_t q = (size_t)v * 384 + lane * 4;
    uint2 h0 = *reinterpret_cast<const uint2*>(&TxH[q]);
    uint2 l0 = *reinterpret_cast<const uint2*>(&TxL[q]);
    float2 t0a = rec2(h0.x, l0.x), t0b = rec2(h0.y, l0.y);
    acc.x = 2.f * acc.x - t0a.x; acc.y = 2.f * acc.y - t0a.y;
    acc.z = 2.f * acc.z - t0b.x; acc.w = 2.f * acc.w - t0b.y;
    size_t o = (size_t)v * 384 + 256 + lane * 4;
    *reinterpret_cast<uint32_t*>(&TxH[o])     = pack2h(acc.x, acc.y);
    *reinterpret_cast<uint32_t*>(&TxH[o + 2]) = pack2h(acc.z, acc.w);
    *reinterpret_cast<uint32_t*>(&TxL[o])     = pack2l(acc.x, acc.y);
    *reinterpret_cast<uint32_t*>(&TxL[o + 2]) = pack2l(acc.z, acc.w);
}

// ---------------- fused attention pooling + concat ----------------
__global__ void pool_kernel(const float* __restrict__ H4, const float* __restrict__ T2,
                            const float* __restrict__ X2, float* __restrict__ hc, int npg) {
    extern __shared__ float sm[];
    float* sH = sm;
    float* sT = sm + npg * 256;
    float* sS = sT + 256;
    int g = blockIdx.x, tid = threadIdx.x;
    const float* Hg = H4 + (size_t)g * npg * 256;
    for (int i = tid; i < npg * 256; i += 256) sH[i] = Hg[i];
    sT[tid] = T2[g * 256 + tid];
    __syncthreads();
    int wid = tid >> 5, lane = tid & 31;
    for (int v = wid; v < npg; v += 8) {
        float s = 0.f;
#pragma unroll
        for (int k = 0; k < 8; k++) s += sH[v * 256 + lane + 32 * k] * sT[lane + 32 * k];
#pragma unroll
        for (int o = 16; o > 0; o >>= 1) s += __shfl_xor_sync(0xffffffffu, s, o);
        if (lane == 0) sS[v] = s;
    }
    __syncthreads();
    float acc = 0.f;
    for (int v = 0; v < npg; v++) acc += sH[v * 256 + tid] * sS[v];
    hc[g * C2 + tid] = acc / (float)npg;
    hc[g * C2 + 256 + tid] = X2[g * 256 + tid];
}

// ---------------- BN / classifier ----------------
__global__ void bn_stats(const float* __restrict__ hc, float* __restrict__ mu,
                         float* __restrict__ rstd, int g) {
    int c = blockIdx.x;
    int tid = threadIdx.x;
    __shared__ float red[256];
    float s = 0.f;
    for (int i = tid; i < g; i += 256) s += hc[i * C2 + c];
    red[tid] = s;
    __syncthreads();
    for (int o = 128; o > 0; o >>= 1) {
        if (tid < o) red[tid] += red[tid + o];
        __syncthreads();
    }
    float m = red[0] / (float)g;
    __syncthreads();
    float sq = 0.f;
    for (int i = tid; i < g; i += 256) {
        float d = hc[i * C2 + c] - m;
        sq += d * d;
    }
    red[tid] = sq;
    __syncthreads();
    for (int o = 128; o > 0; o >>= 1) {
        if (tid < o) red[tid] += red[tid + o];
        __syncthreads();
    }
    if (tid == 0) {
        mu[c] = m;
        rstd[c] = rsqrtf(red[0] / (float)g + 1e-5f);
    }
}

__global__ void bn_final(const float* __restrict__ hc, const float* __restrict__ mu,
                         const float* __restrict__ rstd, const float* __restrict__ gamma,
                         const float* __restrict__ beta, const float* __restrict__ W7,
                         const float* __restrict__ b7, float* __restrict__ out) {
    int g = blockIdx.x;
    int tid = threadIdx.x;
    __shared__ float r0[256], r1[256];
    float s0 = 0.f, s1 = 0.f;
    for (int c = tid; c < C2; c += 256) {
        float v = (hc[g * C2 + c] - mu[c]) * rstd[c] * gamma[c] + beta[c];
        s0 += v * W7[c * 2 + 0];
        s1 += v * W7[c * 2 + 1];
    }
    r0[tid] = s0; r1[tid] = s1;
    __syncthreads();
    for (int o = 128; o > 0; o >>= 1) {
        if (tid < o) { r0[tid] += r0[tid + o]; r1[tid] += r1[tid + o]; }
        __syncthreads();
    }
    if (tid == 0) {
        out[g * 2 + 0] = r0[0] + b7[0];
        out[g * 2 + 1] = r1[0] + b7[1];
    }
}

// ---------------- launch ----------------
#define GEMM_SMEM   81920
#define GEMM12_SMEM 102400

static void launch_gemm_s(cudaStream_t s,
                          const bf16* Ah, const bf16* Al, int lda,
                          const bf16* Bh, const bf16* Bl, int ldb, const float* bias,
                          const float* Cin, int ldcin,
                          float* Cf, int ldcf, bf16* Ch, bf16* Cl, int ldch,
                          int M, int N, int K, int act) {
    dim3 grid(N / 128, (M + 127) / 128);
    gemm_bf16x3<<<grid, 256, GEMM_SMEM, s>>>(Ah, Al, lda, Bh, Bl, ldb, bias, Cin, ldcin,
                                             Cf, ldcf, Ch, Cl, ldch, M, K, act);
}

template <typename T>
static T* sym(const void* s) { void* p; cudaGetSymbolAddress(&p, s); return (T*)p; }

extern "C" void kernel_launch(void* const* d_in, const int* in_sizes, int n_in,
                              void* d_out, int out_size) {
    const float* features = (const float*)d_in[0];
    const int*   edge     = (const int*)d_in[1];
    const float* xLx      = (const float*)d_in[3];
    const float* W1 = (const float*)d_in[4];  const float* b1 = (const float*)d_in[5];
    const float* W2 = (const float*)d_in[6];  const float* b2 = (const float*)d_in[7];
    const float* chebW = (const float*)d_in[8]; const float* chebb = (const float*)d_in[9];
    const float* W3 = (const float*)d_in[10]; const float* b3 = (const float*)d_in[11];
    const float* W4 = (const float*)d_in[12]; const float* b4 = (const float*)d_in[13];
    const float* W5 = (const float*)d_in[14]; const float* b5 = (const float*)d_in[15];
    const float* W6 = (const float*)d_in[16]; const float* b6 = (const float*)d_in[17];
    const float* W8 = (const float*)d_in[18]; const float* b8 = (const float*)d_in[19];
    const float* W9 = (const float*)d_in[20]; const float* b9 = (const float*)d_in[21];
    const float* W7 = (const float*)d_in[22]; const float* b7 = (const float*)d_in[23];
    const float* gamma = (const float*)d_in[24]; const float* beta = (const float*)d_in[25];
    float* out = (float*)d_out;

    int n = in_sizes[0] / F_DIM;   // 100000
    int e = in_sizes[1] / 2;       // 600000
    int g = in_sizes[3] / F_DIM;   // 1000
    int npg = n / g;               // 100

    int pool_smem = (npg * 256 + 256 + npg) * 4;

    static cudaStream_t sB = nullptr;
    static cudaEvent_t evFork = nullptr, evGraphReady = nullptr, evTx0 = nullptr,
                       evGa = nullptr, evSideDone = nullptr;
    static bool init_done = false;
    if (!init_done) {
        cudaFuncSetAttribute(gemm_bf16x3, cudaFuncAttributeMaxDynamicSharedMemorySize, GEMM_SMEM);
        cudaFuncSetAttribute(gemm12, cudaFuncAttributeMaxDynamicSharedMemorySize, GEMM12_SMEM);
        cudaFuncSetAttribute(pool_kernel, cudaFuncAttributeMaxDynamicSharedMemorySize, 112 * 1024);
        cudaStreamCreateWithFlags(&sB, cudaStreamNonBlocking);
        cudaEventCreateWithFlags(&evFork, cudaEventDisableTiming);
        cudaEventCreateWithFlags(&evGraphReady, cudaEventDisableTiming);
        cudaEventCreateWithFlags(&evTx0, cudaEventDisableTiming);
        cudaEventCreateWithFlags(&evGa, cudaEventDisableTiming);
        cudaEventCreateWithFlags(&evSideDone, cudaEventDisableTiming);
        init_done = true;
    }

    bf16 *featH = sym<bf16>(&d_featH), *featL = sym<bf16>(&d_featL);
    bf16 *TxH = sym<bf16>(&d_TxH), *TxL = sym<bf16>(&d_TxL);
    float* H3f = sym<float>(&d_H3f);
    bf16 *H3H = sym<bf16>(&d_H3H), *H3L = sym<bf16>(&d_H3L);
    float* H4 = sym<float>(&d_H4);
    float *deg = sym<float>(&d_deg), *ew = sym<float>(&d_ew);
    int *cnt = sym<int>(&d_cnt), *elist = sym<int>(&d_elist);
    float *T2 = sym<float>(&d_T2), *X2 = sym<float>(&d_X2);
    float *hc = sym<float>(&d_hc), *mu = sym<float>(&d_mu), *rstd = sym<float>(&d_rstd);
    float *zero = sym<float>(&d_zero);
    bf16 *W1tH = sym<bf16>(&d_W1tH), *W1tL = sym<bf16>(&d_W1tL);
    bf16 *W2tH = sym<bf16>(&d_W2tH), *W2tL = sym<bf16>(&d_W2tL);
    bf16 *WcH = sym<bf16>(&d_WcH), *WcL = sym<bf16>(&d_WcL);
    bf16 *W4tH = sym<bf16>(&d_W4tH), *W4tL = sym<bf16>(&d_W4tL);
    bf16 *Wc2H = sym<bf16>(&d_Wc2H), *Wc2L = sym<bf16>(&d_Wc2L);
    bf16 *W8tH = sym<bf16>(&d_W8tH), *W8tL = sym<bf16>(&d_W8tL);
    bf16 *W9tH = sym<bf16>(&d_W9tH), *W9tL = sym<bf16>(&d_W9tL);
    float *b3c = sym<float>(&d_b3c), *bx = sym<float>(&d_bx);
    bf16 *xLxH = sym<bf16>(&d_xLxH), *xLxL = sym<bf16>(&d_xLxL);
    bf16 *T1H = sym<bf16>(&d_T1H), *T1L = sym<bf16>(&d_T1L);

    const int* src = edge;
    const int* dst = edge + e;

    // ---- fork side stream (record precedes wait in enqueue order) ----
    cudaEventRecord(evFork, 0);
    cudaStreamWaitEvent(sB, evFork, 0);

    // ---- side chain part 1 (stream sB) ----
    zero_dc<<<(n + 255) / 256, 256, 0, sB>>>(deg, cnt, n);
    build_graph<<<(e + 255) / 256, 256, 0, sB>>>(src, dst, e, deg, cnt, elist);
    ew_kernel<<<(e + 255) / 256, 256, 0, sB>>>(src, dst, deg, ew, e);
    cudaEventRecord(evGraphReady, sB);     // gates props (recorded before its wait below)
    split_contig<<<(g * 128 + 255) / 256, 256, 0, sB>>>(xLx, xLxH, xLxL, g * 128);
    transpose3<<<640, 256, 0, sB>>>(W4, W4tH, W4tL, W8, W8tH, W8tL, W9, W9tH, W9tL);
    build_wcombo<<<385, 256, 0, sB>>>(chebW, W3, chebb, b3, WcH, WcL, b3c);
    build_wc2<<<129, 256, 0, sB>>>(W5, W6, b5, b6, Wc2H, Wc2L, bx);
    launch_gemm_s(sB, xLxH, xLxL, 128, W8tH, W8tL, 128, b8, nullptr, 0,
                  nullptr, 0, T1H, T1L, 256, g, 256, 128, 1);
    launch_gemm_s(sB, T1H, T1L, 256, W9tH, W9tL, 256, b9, nullptr, 0,
                  T2, 256, nullptr, nullptr, 0, g, 256, 256, 1);
    launch_gemm_s(sB, xLxH, xLxL, 128, Wc2H, Wc2L, 128, bx, nullptr, 0,
                  X2, 256, nullptr, nullptr, 0, g, 256, 128, 1);
    cudaEventRecord(evSideDone, sB);       // T2, X2 ready (gates pool)

    // ---- main chain part 1 (stream 0): up through gemm12, record evTx0 ----
    split_contig<<<(n * 128 + 255) / 256, 256>>>(features, featH, featL, n * 128);
    transpose_w12<<<128, 256>>>(W1, W1tH, W1tL, W2, W2tH, W2tL);
    gemm12<<<(n + 127) / 128, 256, GEMM12_SMEM>>>(featH, featL, W1tH, W1tL, b1,
                                                  W2tH, W2tL, b2, TxH, TxL, n);
    cudaEventRecord(evTx0, 0);             // Tx0 splits ready

    // ---- G_a on side stream (wait enqueued AFTER evTx0 record) ----
    cudaStreamWaitEvent(sB, evTx0, 0);
    launch_gemm_s(sB, TxH, TxL, 384, WcH, WcL, 384, zero, nullptr, 0,
                  H3f, 256, nullptr, nullptr, 0, n, 256, 128, 0);
    cudaEventRecord(evGa, sB);

    // ---- main chain part 2 ----
    cudaStreamWaitEvent(0, evGraphReady, 0);
    prop_split1<<<(n * 32 + 255) / 256, 256>>>(TxH, TxL, ew, src, elist, cnt, n);
    prop_split2<<<(n * 32 + 255) / 256, 256>>>(TxH, TxL, ew, src, elist, cnt, n);

    // G_b: Tx1/Tx2 remainder (K=256), accumulates H3f, bias+act, emits splits.
    cudaStreamWaitEvent(0, evGa, 0);
    launch_gemm_s(0, TxH + 128, TxL + 128, 384, WcH + 128, WcL + 128, 384, b3c,
                  H3f, 256, nullptr, 0, H3H, H3L, 256, n, 256, 256, 1);
    launch_gemm_s(0, H3H, H3L, 256, W4tH, W4tL, 256, b4, nullptr, 0,
                  H4, 256, nullptr, nullptr, 0, n, 256, 256, 1);

    cudaStreamWaitEvent(0, evSideDone, 0);
    pool_kernel<<<g, 256, pool_smem>>>(H4, T2, X2, hc, npg);
    bn_stats<<<C2, 256>>>(hc, mu, rstd, g);
    bn_final<<<g, 256>>>(hc, mu, rstd, gamma, beta, W7, b7, out);
}

// round 16
// speedup vs baseline: 1.1281x; 1.1281x over previous
#include <cuda_runtime.h>
#include <cuda_bf16.h>
#include <cstdint>
#include <math.h>

#define N_NODES 100000
#define F_DIM   128
#define E_EDGES 600000
#define G_GRAPHS 1000
#define HDIM    256
#define C2      (2*HDIM)
#define ECAP    96

typedef __nv_bfloat16 bf16;

// ---------------- scratch (static device memory; no allocs) ----------------
__device__ bf16  d_featH[(size_t)N_NODES * 128];
__device__ bf16  d_featL[(size_t)N_NODES * 128];
__device__ bf16  d_TxH [(size_t)N_NODES * 384];   // [Tx0|Tx1|Tx2] hi
__device__ bf16  d_TxL [(size_t)N_NODES * 384];   // [Tx0|Tx1|Tx2] lo
__device__ bf16  d_H3H [(size_t)N_NODES * 256];
__device__ bf16  d_H3L [(size_t)N_NODES * 256];
__device__ float d_H4  [(size_t)N_NODES * 256];
__device__ float d_deg [N_NODES];
__device__ float d_ew  [E_EDGES];
__device__ int   d_cnt [N_NODES];
__device__ int   d_elist[(size_t)N_NODES * ECAP];
__device__ float d_T2  [G_GRAPHS * HDIM];
__device__ float d_X2  [G_GRAPHS * HDIM];
__device__ float d_hc  [G_GRAPHS * C2];
__device__ float d_mu  [C2];
__device__ float d_rstd[C2];
// bf16 hi/lo transposed weights [N,K]
__device__ bf16 d_W1tH[128*128], d_W1tL[128*128];
__device__ bf16 d_W2tH[128*128], d_W2tL[128*128];
__device__ bf16 d_WcH [256*384], d_WcL [256*384];   // (Wbig@W3)^T
__device__ bf16 d_W4tH[256*256], d_W4tL[256*256];
__device__ bf16 d_Wc2H[256*128], d_Wc2L[256*128];   // (W5@W6)^T
__device__ bf16 d_W8tH[256*128], d_W8tL[256*128];
__device__ bf16 d_W9tH[256*256], d_W9tL[256*256];
__device__ float d_b3c [256];
__device__ float d_bx  [256];
// graph-side activations
__device__ bf16 d_xLxH[G_GRAPHS*128], d_xLxL[G_GRAPHS*128];
__device__ bf16 d_T1H [G_GRAPHS*256], d_T1L [G_GRAPHS*256];

// ---------------- helpers ----------------
__device__ __forceinline__ uint32_t smem_to_u32(const void* p) {
    uint32_t a;
    asm("{ .reg .u64 t; cvta.to.shared.u64 t, %1; cvt.u32.u64 %0, t; }" : "=r"(a) : "l"(p));
    return a;
}
__device__ __forceinline__ void split1(float v, bf16& h, bf16& l) {
    h = __float2bfloat16(v);
    l = __float2bfloat16(v - __bfloat162float(h));
}
__device__ __forceinline__ uint32_t pack2h(float a, float b) {
    __nv_bfloat162 t = __floats2bfloat162_rn(a, b);
    return *reinterpret_cast<uint32_t*>(&t);
}
__device__ __forceinline__ uint32_t pack2l(float a, float b) {
    float ra = a - __bfloat162float(__float2bfloat16(a));
    float rb = b - __bfloat162float(__float2bfloat16(b));
    __nv_bfloat162 t = __floats2bfloat162_rn(ra, rb);
    return *reinterpret_cast<uint32_t*>(&t);
}
// reconstruct 2 fp32 from packed hi/lo bf16x2
__device__ __forceinline__ float2 rec2(uint32_t h, uint32_t l) {
    __nv_bfloat162 hh = *reinterpret_cast<__nv_bfloat162*>(&h);
    __nv_bfloat162 ll = *reinterpret_cast<__nv_bfloat162*>(&l);
    return make_float2(__bfloat162float(hh.x) + __bfloat162float(ll.x),
                       __bfloat162float(hh.y) + __bfloat162float(ll.y));
}

#define LDMX4(r, addr)                                                          \
    asm volatile("ldmatrix.sync.aligned.m8n8.x4.shared.b16 {%0,%1,%2,%3}, [%4];"\
        : "=r"((r)[0]), "=r"((r)[1]), "=r"((r)[2]), "=r"((r)[3]) : "r"(addr))

#define CP16(dst, src, sz)                                                      \
    asm volatile("cp.async.cg.shared.global [%0], [%1], 16, %2;"                \
        :: "r"(dst), "l"(src), "r"(sz))

#define MMA4(d, a, b0v, b1v)                                                    \
    asm("mma.sync.aligned.m16n8k16.row.col.f32.bf16.bf16.f32 "                  \
        "{%0,%1,%2,%3}, {%4,%5,%6,%7}, {%8,%9}, {%0,%1,%2,%3};"                 \
        : "+f"((d)[0]), "+f"((d)[1]), "+f"((d)[2]), "+f"((d)[3])                \
        : "r"((a)[0]), "r"((a)[1]), "r"((a)[2]), "r"((a)[3]), "r"(b0v), "r"(b1v))

// ---------------- GEMM: C = act(A @ Bt^T + bias), bf16x3 split operands ------
__global__ __launch_bounds__(256, 2)
void gemm_bf16x3(const bf16* __restrict__ Ahi, const bf16* __restrict__ Alo, int lda,
                 const bf16* __restrict__ Bhi, const bf16* __restrict__ Blo, int ldb,
                 const float* __restrict__ bias,
                 float* __restrict__ Cf, int ldcf,
                 bf16* __restrict__ Chi, bf16* __restrict__ Clo, int ldch,
                 int M, int K, int act) {
    extern __shared__ char smem[];
    const uint32_t sbase = smem_to_u32(smem);
    const int tid = threadIdx.x, lane = tid & 31, wid = tid >> 5;
    const int wm = wid >> 2, wn = wid & 3;
    const int bm = blockIdx.y * 128, bn = blockIdx.x * 128;
    const int nch = K >> 5;            // always even

    float acc[4][4][4];
#pragma unroll
    for (int i = 0; i < 4; i++)
#pragma unroll
        for (int j = 0; j < 4; j++)
#pragma unroll
            for (int r = 0; r < 4; r++) acc[i][j][r] = 0.f;

    const int r0 = tid >> 2, ch = tid & 3;
    const int r1 = r0 + 64;
    const uint32_t sz0 = (bm + r0 < M) ? 16u : 0u;
    const uint32_t sz1 = (bm + r1 < M) ? 16u : 0u;
    const char* pA0h = (const char*)(Ahi + (size_t)(bm + r0) * lda + ch * 8);
    const char* pA0l = (const char*)(Alo + (size_t)(bm + r0) * lda + ch * 8);
    const char* pA1h = (const char*)(Ahi + (size_t)(bm + r1) * lda + ch * 8);
    const char* pA1l = (const char*)(Alo + (size_t)(bm + r1) * lda + ch * 8);
    const char* pB0h = (const char*)(Bhi + (size_t)(bn + r0) * ldb + ch * 8);
    const char* pB0l = (const char*)(Blo + (size_t)(bn + r0) * ldb + ch * 8);
    const char* pB1h = (const char*)(Bhi + (size_t)(bn + r1) * ldb + ch * 8);
    const char* pB1l = (const char*)(Blo + (size_t)(bn + r1) * ldb + ch * 8);
    const uint32_t dA0 = sbase + r0 * 80 + ch * 16;
    const uint32_t dA1 = dA0 + 64 * 80;
    const uint32_t dB0 = dA0 + 20480;
    const uint32_t dB1 = dA1 + 20480;

    auto stage_load = [&](int c, uint32_t so) {
        const uint32_t ko = (uint32_t)c * 64u;
        CP16(dA0 + so,         pA0h + ko, sz0);
        CP16(dA0 + so + 10240, pA0l + ko, sz0);
        CP16(dA1 + so,         pA1h + ko, sz1);
        CP16(dA1 + so + 10240, pA1l + ko, sz1);
        CP16(dB0 + so,         pB0h + ko, 16u);
        CP16(dB0 + so + 10240, pB0l + ko, 16u);
        CP16(dB1 + so,         pB1h + ko, 16u);
        CP16(dB1 + so + 10240, pB1l + ko, 16u);
    };

    stage_load(0, 0);
    asm volatile("cp.async.commit_group;");
    stage_load(1, 40960);
    asm volatile("cp.async.commit_group;");

    const int rsub = ((lane >> 3) & 1) * 8 + (lane & 7);
    const uint32_t csel = (uint32_t)((lane >> 4) << 4);
    const uint32_t aBase = sbase + (uint32_t)(wm * 64 + rsub) * 80 + csel;
    const uint32_t bBase = sbase + 20480 + (uint32_t)(wn * 32 + rsub) * 80 + csel;

    auto chunk = [&](int c, uint32_t so) {
        asm volatile("cp.async.wait_group 1;");
        __syncthreads();
#pragma unroll
        for (int kt = 0; kt < 2; kt++) {
            const uint32_t ko = so + (uint32_t)(kt * 32);
            uint32_t bh[2][4], bl[2][4];
#pragma unroll
            for (int np = 0; np < 2; np++) {
                LDMX4(bh[np], bBase + ko + np * 1280);
                LDMX4(bl[np], bBase + ko + np * 1280 + 10240);
            }
#pragma unroll
            for (int i = 0; i < 4; i++) {
                uint32_t ah[4], al[4];
                LDMX4(ah, aBase + ko + i * 1280);
                LDMX4(al, aBase + ko + i * 1280 + 10240);
#pragma unroll
                for (int j = 0; j < 4; j++) {
                    const int np = j >> 1, o = j & 1;
                    MMA4(acc[i][j], ah, bh[np][o], bh[np][2 + o]);
                    MMA4(acc[i][j], ah, bl[np][o], bl[np][2 + o]);
                    MMA4(acc[i][j], al, bh[np][o], bh[np][2 + o]);
                }
            }
        }
        __syncthreads();
        if (c + 2 < nch) stage_load(c + 2, so);
        asm volatile("cp.async.commit_group;");
    };

    for (int c = 0; c < nch; c += 2) {
        chunk(c, 0);
        chunk(c + 1, 40960);
    }

    const int g = lane >> 2, tg = lane & 3;
#pragma unroll
    for (int i = 0; i < 4; i++) {
        const int row0 = bm + wm * 64 + i * 16 + g;
#pragma unroll
        for (int j = 0; j < 4; j++) {
            const int col = bn + wn * 32 + j * 8 + tg * 2;
            const float b0 = bias[col], b1 = bias[col + 1];
#pragma unroll
            for (int h = 0; h < 2; h++) {
                const int row = row0 + h * 8;
                if (row >= M) continue;
                float v0 = acc[i][j][h * 2 + 0] + b0;
                float v1 = acc[i][j][h * 2 + 1] + b1;
                if (act) {
                    v0 = v0 > 0.f ? v0 : 0.01f * v0;
                    v1 = v1 > 0.f ? v1 : 0.01f * v1;
                }
                if (Cf) {
                    float2 fv = make_float2(v0, v1);
                    *reinterpret_cast<float2*>(&Cf[(size_t)row * ldcf + col]) = fv;
                }
                if (Chi) {
                    *reinterpret_cast<uint32_t*>(&Chi[(size_t)row * ldch + col]) = pack2h(v0, v1);
                    *reinterpret_cast<uint32_t*>(&Clo[(size_t)row * ldch + col]) = pack2l(v0, v1);
                }
            }
        }
    }
}

// ---------------- fused W1+W2 GEMM (no fp32 output) --------------------------
__global__ __launch_bounds__(256, 2)
void gemm12(const bf16* __restrict__ fH, const bf16* __restrict__ fL,
            const bf16* __restrict__ W1H, const bf16* __restrict__ W1L,
            const float* __restrict__ b1,
            const bf16* __restrict__ W2H, const bf16* __restrict__ W2L,
            const float* __restrict__ b2,
            bf16* __restrict__ TxH, bf16* __restrict__ TxL,
            int M) {
    extern __shared__ char smem[];
    const uint32_t sbase = smem_to_u32(smem);
    const int tid = threadIdx.x, lane = tid & 31, wid = tid >> 5;
    const int wm = wid >> 2, wn = wid & 3;
    const int bm = blockIdx.x * 128;

    float acc[4][4][4];
#pragma unroll
    for (int i = 0; i < 4; i++)
#pragma unroll
        for (int j = 0; j < 4; j++)
#pragma unroll
            for (int r = 0; r < 4; r++) acc[i][j][r] = 0.f;

    const int r0 = tid >> 2, ch = tid & 3;
    const int r1 = r0 + 64;
    const uint32_t sz0 = (bm + r0 < M) ? 16u : 0u;
    const uint32_t sz1 = (bm + r1 < M) ? 16u : 0u;
    const uint32_t dA0 = sbase + r0 * 80 + ch * 16;
    const uint32_t dA1 = dA0 + 64 * 80;
    const uint32_t dB0 = dA0 + 20480;
    const uint32_t dB1 = dA1 + 20480;

    {
        const char* pA0h = (const char*)(fH + (size_t)(bm + r0) * 128 + ch * 8);
        const char* pA0l = (const char*)(fL + (size_t)(bm + r0) * 128 + ch * 8);
        const char* pA1h = (const char*)(fH + (size_t)(bm + r1) * 128 + ch * 8);
        const char* pA1l = (const char*)(fL + (size_t)(bm + r1) * 128 + ch * 8);
        const char* pB0h = (const char*)(W1H + (size_t)r0 * 128 + ch * 8);
        const char* pB0l = (const char*)(W1L + (size_t)r0 * 128 + ch * 8);
        const char* pB1h = (const char*)(W1H + (size_t)r1 * 128 + ch * 8);
        const char* pB1l = (const char*)(W1L + (size_t)r1 * 128 + ch * 8);

        auto stage_load = [&](int c, uint32_t so) {
            const uint32_t ko = (uint32_t)c * 64u;
            CP16(dA0 + so,         pA0h + ko, sz0);
            CP16(dA0 + so + 10240, pA0l + ko, sz0);
            CP16(dA1 + so,         pA1h + ko, sz1);
            CP16(dA1 + so + 10240, pA1l + ko, sz1);
            CP16(dB0 + so,         pB0h + ko, 16u);
            CP16(dB0 + so + 10240, pB0l + ko, 16u);
            CP16(dB1 + so,         pB1h + ko, 16u);
            CP16(dB1 + so + 10240, pB1l + ko, 16u);
        };

        stage_load(0, 0);
        asm volatile("cp.async.commit_group;");
        stage_load(1, 40960);
        asm volatile("cp.async.commit_group;");

        const int rsub = ((lane >> 3) & 1) * 8 + (lane & 7);
        const uint32_t csel = (uint32_t)((lane >> 4) << 4);
        const uint32_t aBase = sbase + (uint32_t)(wm * 64 + rsub) * 80 + csel;
        const uint32_t bBase = sbase + 20480 + (uint32_t)(wn * 32 + rsub) * 80 + csel;

        auto chunk = [&](int c, uint32_t so) {
            asm volatile("cp.async.wait_group 1;");
            __syncthreads();
#pragma unroll
            for (int kt = 0; kt < 2; kt++) {
                const uint32_t ko = so + (uint32_t)(kt * 32);
                uint32_t bh[2][4], bl[2][4];
#pragma unroll
                for (int np = 0; np < 2; np++) {
                    LDMX4(bh[np], bBase + ko + np * 1280);
                    LDMX4(bl[np], bBase + ko + np * 1280 + 10240);
                }
#pragma unroll
                for (int i = 0; i < 4; i++) {
                    uint32_t ah[4], al[4];
                    LDMX4(ah, aBase + ko + i * 1280);
                    LDMX4(al, aBase + ko + i * 1280 + 10240);
#pragma unroll
                    for (int j = 0; j < 4; j++) {
                        const int np = j >> 1, o = j & 1;
                        MMA4(acc[i][j], ah, bh[np][o], bh[np][2 + o]);
                        MMA4(acc[i][j], ah, bl[np][o], bl[np][2 + o]);
                        MMA4(acc[i][j], al, bh[np][o], bh[np][2 + o]);
                    }
                }
            }
            __syncthreads();
            if (c + 2 < 4) stage_load(c + 2, so);
            asm volatile("cp.async.commit_group;");
        };

        chunk(0, 0);
        chunk(1, 40960);
        chunk(2, 0);
        chunk(3, 40960);
    }

    const int g = lane >> 2, tg = lane & 3;
#pragma unroll
    for (int i = 0; i < 4; i++) {
        const int crow = wm * 64 + i * 16 + g;
#pragma unroll
        for (int j = 0; j < 4; j++) {
            const int col = wn * 32 + j * 8 + tg * 2;
            const float b0 = b1[col], b1v = b1[col + 1];
            const int c2 = col >> 5, kin = col & 31;
            const uint32_t base = sbase + (uint32_t)c2 * 20480 + kin * 2;
#pragma unroll
            for (int h = 0; h < 2; h++) {
                float v0 = acc[i][j][h * 2 + 0] + b0;
                float v1 = acc[i][j][h * 2 + 1] + b1v;
                v0 = v0 > 0.f ? v0 : 0.01f * v0;
                v1 = v1 > 0.f ? v1 : 0.01f * v1;
                const uint32_t a = base + (uint32_t)(crow + h * 8) * 80;
                *reinterpret_cast<uint32_t*>(smem + (a - sbase))         = pack2h(v0, v1);
                *reinterpret_cast<uint32_t*>(smem + (a - sbase) + 10240) = pack2l(v0, v1);
                acc[i][j][h * 2 + 0] = 0.f;
                acc[i][j][h * 2 + 1] = 0.f;
            }
        }
    }
    __syncthreads();

    {
        const char* pW0h = (const char*)(W2H + (size_t)r0 * 128 + ch * 8);
        const char* pW0l = (const char*)(W2L + (size_t)r0 * 128 + ch * 8);
        const char* pW1h = (const char*)(W2H + (size_t)r1 * 128 + ch * 8);
        const char* pW1l = (const char*)(W2L + (size_t)r1 * 128 + ch * 8);
        const uint32_t eB0 = sbase + 81920 + r0 * 80 + ch * 16;
        const uint32_t eB1 = eB0 + 64 * 80;

        const int rsub = ((lane >> 3) & 1) * 8 + (lane & 7);
        const uint32_t csel = (uint32_t)((lane >> 4) << 4);
        const uint32_t aB2 = sbase + (uint32_t)(wm * 64 + rsub) * 80 + csel;
        const uint32_t bB2 = sbase + 81920 + (uint32_t)(wn * 32 + rsub) * 80 + csel;

        for (int c2 = 0; c2 < 4; c2++) {
            const uint32_t ko = (uint32_t)c2 * 64u;
            CP16(eB0,         pW0h + ko, 16u);
            CP16(eB0 + 10240, pW0l + ko, 16u);
            CP16(eB1,         pW1h + ko, 16u);
            CP16(eB1 + 10240, pW1l + ko, 16u);
            asm volatile("cp.async.commit_group;");
            asm volatile("cp.async.wait_group 0;");
            __syncthreads();
            const uint32_t aC = aB2 + (uint32_t)c2 * 20480;
#pragma unroll
            for (int kt = 0; kt < 2; kt++) {
                const uint32_t ko2 = (uint32_t)(kt * 32);
                uint32_t bh[2][4], bl[2][4];
#pragma unroll
                for (int np = 0; np < 2; np++) {
                    LDMX4(bh[np], bB2 + ko2 + np * 1280);
                    LDMX4(bl[np], bB2 + ko2 + np * 1280 + 10240);
                }
#pragma unroll
                for (int i = 0; i < 4; i++) {
                    uint32_t ah[4], al[4];
                    LDMX4(ah, aC + ko2 + i * 1280);
                    LDMX4(al, aC + ko2 + i * 1280 + 10240);
#pragma unroll
                    for (int j = 0; j < 4; j++) {
                        const int np = j >> 1, o = j & 1;
                        MMA4(acc[i][j], ah, bh[np][o], bh[np][2 + o]);
                        MMA4(acc[i][j], ah, bl[np][o], bl[np][2 + o]);
                        MMA4(acc[i][j], al, bh[np][o], bh[np][2 + o]);
                    }
                }
            }
            __syncthreads();
        }
    }

#pragma unroll
    for (int i = 0; i < 4; i++) {
        const int row0 = bm + wm * 64 + i * 16 + g;
#pragma unroll
        for (int j = 0; j < 4; j++) {
            const int col = wn * 32 + j * 8 + tg * 2;
            const float c0 = b2[col], c1 = b2[col + 1];
#pragma unroll
            for (int h = 0; h < 2; h++) {
                const int row = row0 + h * 8;
                if (row >= M) continue;
                float v0 = acc[i][j][h * 2 + 0] + c0;
                float v1 = acc[i][j][h * 2 + 1] + c1;
                v0 = v0 > 0.f ? v0 : 0.01f * v0;
                v1 = v1 > 0.f ? v1 : 0.01f * v1;
                *reinterpret_cast<uint32_t*>(&TxH[(size_t)row * 384 + col]) = pack2h(v0, v1);
                *reinterpret_cast<uint32_t*>(&TxL[(size_t)row * 384 + col]) = pack2l(v0, v1);
            }
        }
    }
}

// ---------------- weight-combination builders ----------------
__global__ void build_wcombo(const float* __restrict__ chebW, const float* __restrict__ W3,
                             const float* __restrict__ chebb, const float* __restrict__ b3,
                             bf16* __restrict__ WcH, bf16* __restrict__ WcL,
                             float* __restrict__ b3c) {
    int c = threadIdx.x;
    if (blockIdx.x == 384) {
        float acc = b3[c];
        for (int n = 0; n < 512; n++) acc += chebb[n] * W3[n * 256 + c];
        b3c[c] = acc;
        return;
    }
    __shared__ float wrow[512];
    int k = blockIdx.x;
    int kk = k >> 7, i = k & 127;
    for (int idx = c; idx < 512; idx += 256) {
        int w = idx >> 7, j = idx & 127;
        wrow[idx] = chebW[(((w * 3) + kk) * 128 + i) * 128 + j];
    }
    __syncthreads();
    float acc = 0.f;
#pragma unroll 8
    for (int j = 0; j < 512; j++) acc += wrow[j] * W3[j * 256 + c];
    bf16 h, l; split1(acc, h, l);
    WcH[c * 384 + k] = h; WcL[c * 384 + k] = l;
}

__global__ void build_wc2(const float* __restrict__ W5, const float* __restrict__ W6,
                          const float* __restrict__ b5, const float* __restrict__ b6,
                          bf16* __restrict__ Wc2H, bf16* __restrict__ Wc2L,
                          float* __restrict__ bx) {
    int c = threadIdx.x;
    if (blockIdx.x == 128) {
        float acc = b6[c];
        for (int j = 0; j < 256; j++) acc += b5[j] * W6[j * 256 + c];
        bx[c] = acc;
        return;
    }
    __shared__ float wrow[256];
    int k = blockIdx.x;
    wrow[c] = W5[k * 256 + c];
    __syncthreads();
    float acc = 0.f;
#pragma unroll 8
    for (int j = 0; j < 256; j++) acc += wrow[j] * W6[j * 256 + c];
    bf16 h, l; split1(acc, h, l);
    Wc2H[c * 128 + k] = h; Wc2L[c * 128 + k] = l;
}

// ---------------- prep / convert kernels ----------------
__global__ void zero_dc(float* deg, int* cnt, int n) {
    int i = blockIdx.x * 256 + threadIdx.x;
    if (i < n) { deg[i] = 0.f; cnt[i] = 0; }
}
__global__ void split_contig(const float* __restrict__ s, bf16* __restrict__ h,
                             bf16* __restrict__ l, int n) {
    int i = blockIdx.x * 256 + threadIdx.x;
    if (i < n) { bf16 hh, ll; split1(s[i], hh, ll); h[i] = hh; l[i] = ll; }
}
__global__ void transpose_w12(const float* __restrict__ W1, bf16* __restrict__ W1tH, bf16* __restrict__ W1tL,
                              const float* __restrict__ W2, bf16* __restrict__ W2tH, bf16* __restrict__ W2tL) {
    int idx = blockIdx.x * 256 + threadIdx.x;
    if (idx >= 32768) return;
    const float* W = (idx < 16384) ? W1 : W2;
    bf16* Th = (idx < 16384) ? W1tH : W2tH;
    bf16* Tl = (idx < 16384) ? W1tL : W2tL;
    int t = idx & 16383;
    int k = t >> 7, n = t & 127;
    bf16 h, l; split1(W[t], h, l);
    Th[n * 128 + k] = h; Tl[n * 128 + k] = l;
}
__global__ void transpose3(const float* __restrict__ W4, bf16* __restrict__ W4tH, bf16* __restrict__ W4tL,
                           const float* __restrict__ W8, bf16* __restrict__ W8tH, bf16* __restrict__ W8tL,
                           const float* __restrict__ W9, bf16* __restrict__ W9tH, bf16* __restrict__ W9tL) {
    int idx = blockIdx.x * 256 + threadIdx.x;
    const float* W; bf16 *Th, *Tl; int K, t;
    if (idx < 65536)       { W = W4; Th = W4tH; Tl = W4tL; K = 256; t = idx; }
    else if (idx < 98304)  { W = W8; Th = W8tH; Tl = W8tL; K = 128; t = idx - 65536; }
    else if (idx < 163840) { W = W9; Th = W9tH; Tl = W9tL; K = 256; t = idx - 98304; }
    else return;
    int k = t / 256, n = t % 256;
    bf16 h, l; split1(W[t], h, l);
    Th[n * K + k] = h; Tl[n * K + k] = l;
}

// ---------------- graph structure ----------------
__global__ void build_graph(const int* __restrict__ src, const int* __restrict__ dst, int e,
                            float* __restrict__ deg, int* __restrict__ cnt,
                            int* __restrict__ elist) {
    int i = blockIdx.x * 256 + threadIdx.x;
    if (i >= e) return;
    atomicAdd(&deg[src[i]], 1.0f);
    int d = dst[i];
    int p = atomicAdd(&cnt[d], 1);
    if (p < ECAP) elist[(size_t)d * ECAP + p] = i;
}
__global__ void ew_kernel(const int* __restrict__ src, const int* __restrict__ dst,
                          const float* __restrict__ deg, float* __restrict__ ew, int e) {
    int i = blockIdx.x * 256 + threadIdx.x;
    if (i >= e) return;
    float ds = rsqrtf(fmaxf(deg[src[i]], 1.f));
    float dv = deg[dst[i]];
    float dd = (dv > 0.f) ? rsqrtf(fmaxf(dv, 1.f)) : 0.f;
    ew[i] = -(ds * dd);
}

// prop #1: Tx1 = P(Tx0). Reads hi/lo splits (cols 0-127), reconstructs fp32,
// writes hi/lo of Tx1 (cols 128-255). Warp per node, no atomics.
__global__ void prop_split1(bf16* __restrict__ TxH, bf16* __restrict__ TxL,
                            const float* __restrict__ ew,
                            const int* __restrict__ src, const int* __restrict__ elist,
                            const int* __restrict__ cnt, int n) {
    int v = (blockIdx.x * 256 + threadIdx.x) >> 5;
    int lane = threadIdx.x & 31;
    if (v >= n) return;
    int c = cnt[v];
    if (c > ECAP) c = ECAP;
    float4 acc = make_float4(0.f, 0.f, 0.f, 0.f);
    const int* el = &elist[(size_t)v * ECAP];
    for (int i = 0; i < c; i++) {
        int eid = el[i];
        int s = src[eid];
        float w = ew[eid];
        size_t p = (size_t)s * 384 + lane * 4;
        uint2 h = *reinterpret_cast<const uint2*>(&TxH[p]);
        uint2 l = *reinterpret_cast<const uint2*>(&TxL[p]);
        float2 a = rec2(h.x, l.x), b = rec2(h.y, l.y);
        acc.x += w * a.x; acc.y += w * a.y; acc.z += w * b.x; acc.w += w * b.y;
    }
    size_t o = (size_t)v * 384 + 128 + lane * 4;
    *reinterpret_cast<uint32_t*>(&TxH[o])     = pack2h(acc.x, acc.y);
    *reinterpret_cast<uint32_t*>(&TxH[o + 2]) = pack2h(acc.z, acc.w);
    *reinterpret_cast<uint32_t*>(&TxL[o])     = pack2l(acc.x, acc.y);
    *reinterpret_cast<uint32_t*>(&TxL[o + 2]) = pack2l(acc.z, acc.w);
}

// prop #2: Tx2 = 2*P(Tx1) - Tx0. Reads Tx1 splits (cols 128-255) of neighbors
// and Tx0 splits (cols 0-127) of v; writes hi/lo of Tx2 (cols 256-383).
__global__ void prop_split2(bf16* __restrict__ TxH, bf16* __restrict__ TxL,
                            const float* __restrict__ ew,
                            const int* __restrict__ src, const int* __restrict__ elist,
                            const int* __restrict__ cnt, int n) {
    int v = (blockIdx.x * 256 + threadIdx.x) >> 5;
    int lane = threadIdx.x & 31;
    if (v >= n) return;
    int c = cnt[v];
    if (c > ECAP) c = ECAP;
    float4 acc = make_float4(0.f, 0.f, 0.f, 0.f);
    const int* el = &elist[(size_t)v * ECAP];
    for (int i = 0; i < c; i++) {
        int eid = el[i];
        int s = src[eid];
        float w = ew[eid];
        size_t p = (size_t)s * 384 + 128 + lane * 4;
        uint2 h = *reinterpret_cast<const uint2*>(&TxH[p]);
        uint2 l = *reinterpret_cast<const uint2*>(&TxL[p]);
        float2 a = rec2(h.x, l.x), b = rec2(h.y, l.y);
        acc.x += w * a.x; acc.y += w * a.y; acc.z += w * b.x; acc.w += w * b.y;
    }
    size_t q = (size_t)v * 384 + lane * 4;
    uint2 h0 = *reinterpret_cast<const uint2*>(&TxH[q]);
    uint2 l0 = *reinterpret_cast<const uint2*>(&TxL[q]);
    float2 t0a = rec2(h0.x, l0.x), t0b = rec2(h0.y, l0.y);
    acc.x = 2.f * acc.x - t0a.x; acc.y = 2.f * acc.y - t0a.y;
    acc.z = 2.f * acc.z - t0b.x; acc.w = 2.f * acc.w - t0b.y;
    size_t o = (size_t)v * 384 + 256 + lane * 4;
    *reinterpret_cast<uint32_t*>(&TxH[o])     = pack2h(acc.x, acc.y);
    *reinterpret_cast<uint32_t*>(&TxH[o + 2]) = pack2h(acc.z, acc.w);
    *reinterpret_cast<uint32_t*>(&TxL[o])     = pack2l(acc.x, acc.y);
    *reinterpret_cast<uint32_t*>(&TxL[o + 2]) = pack2l(acc.z, acc.w);
}

// ---------------- fused attention pooling + concat ----------------
__global__ void pool_kernel(const float* __restrict__ H4, const float* __restrict__ T2,
                            const float* __restrict__ X2, float* __restrict__ hc, int npg) {
    extern __shared__ float sm[];
    float* sH = sm;
    float* sT = sm + npg * 256;
    float* sS = sT + 256;
    int g = blockIdx.x, tid = threadIdx.x;
    const float* Hg = H4 + (size_t)g * npg * 256;
    for (int i = tid; i < npg * 256; i += 256) sH[i] = Hg[i];
    sT[tid] = T2[g * 256 + tid];
    __syncthreads();
    int wid = tid >> 5, lane = tid & 31;
    for (int v = wid; v < npg; v += 8) {
        float s = 0.f;
#pragma unroll
        for (int k = 0; k < 8; k++) s += sH[v * 256 + lane + 32 * k] * sT[lane + 32 * k];
#pragma unroll
        for (int o = 16; o > 0; o >>= 1) s += __shfl_xor_sync(0xffffffffu, s, o);
        if (lane == 0) sS[v] = s;
    }
    __syncthreads();
    float acc = 0.f;
    for (int v = 0; v < npg; v++) acc += sH[v * 256 + tid] * sS[v];
    hc[g * C2 + tid] = acc / (float)npg;
    hc[g * C2 + 256 + tid] = X2[g * 256 + tid];
}

// ---------------- BN / classifier ----------------
__global__ void bn_stats(const float* __restrict__ hc, float* __restrict__ mu,
                         float* __restrict__ rstd, int g) {
    int c = blockIdx.x;
    int tid = threadIdx.x;
    __shared__ float red[256];
    float s = 0.f;
    for (int i = tid; i < g; i += 256) s += hc[i * C2 + c];
    red[tid] = s;
    __syncthreads();
    for (int o = 128; o > 0; o >>= 1) {
        if (tid < o) red[tid] += red[tid + o];
        __syncthreads();
    }
    float m = red[0] / (float)g;
    __syncthreads();
    float sq = 0.f;
    for (int i = tid; i < g; i += 256) {
        float d = hc[i * C2 + c] - m;
        sq += d * d;
    }
    red[tid] = sq;
    __syncthreads();
    for (int o = 128; o > 0; o >>= 1) {
        if (tid < o) red[tid] += red[tid + o];
        __syncthreads();
    }
    if (tid == 0) {
        mu[c] = m;
        rstd[c] = rsqrtf(red[0] / (float)g + 1e-5f);
    }
}

__global__ void bn_final(const float* __restrict__ hc, const float* __restrict__ mu,
                         const float* __restrict__ rstd, const float* __restrict__ gamma,
                         const float* __restrict__ beta, const float* __restrict__ W7,
                         const float* __restrict__ b7, float* __restrict__ out) {
    int g = blockIdx.x;
    int tid = threadIdx.x;
    __shared__ float r0[256], r1[256];
    float s0 = 0.f, s1 = 0.f;
    for (int c = tid; c < C2; c += 256) {
        float v = (hc[g * C2 + c] - mu[c]) * rstd[c] * gamma[c] + beta[c];
        s0 += v * W7[c * 2 + 0];
        s1 += v * W7[c * 2 + 1];
    }
    r0[tid] = s0; r1[tid] = s1;
    __syncthreads();
    for (int o = 128; o > 0; o >>= 1) {
        if (tid < o) { r0[tid] += r0[tid + o]; r1[tid] += r1[tid + o]; }
        __syncthreads();
    }
    if (tid == 0) {
        out[g * 2 + 0] = r0[0] + b7[0];
        out[g * 2 + 1] = r1[0] + b7[1];
    }
}

// ---------------- launch ----------------
#define GEMM_SMEM   81920
#define GEMM12_SMEM 102400

static void launch_gemm_s(cudaStream_t s,
                          const bf16* Ah, const bf16* Al, int lda,
                          const bf16* Bh, const bf16* Bl, int ldb, const float* bias,
                          float* Cf, int ldcf, bf16* Ch, bf16* Cl, int ldch,
                          int M, int N, int K, int act) {
    dim3 grid(N / 128, (M + 127) / 128);
    gemm_bf16x3<<<grid, 256, GEMM_SMEM, s>>>(Ah, Al, lda, Bh, Bl, ldb, bias,
                                             Cf, ldcf, Ch, Cl, ldch, M, K, act);
}

template <typename T>
static T* sym(const void* s) { void* p; cudaGetSymbolAddress(&p, s); return (T*)p; }

extern "C" void kernel_launch(void* const* d_in, const int* in_sizes, int n_in,
                              void* d_out, int out_size) {
    const float* features = (const float*)d_in[0];
    const int*   edge     = (const int*)d_in[1];
    const float* xLx      = (const float*)d_in[3];
    const float* W1 = (const float*)d_in[4];  const float* b1 = (const float*)d_in[5];
    const float* W2 = (const float*)d_in[6];  const float* b2 = (const float*)d_in[7];
    const float* chebW = (const float*)d_in[8]; const float* chebb = (const float*)d_in[9];
    const float* W3 = (const float*)d_in[10]; const float* b3 = (const float*)d_in[11];
    const float* W4 = (const float*)d_in[12]; const float* b4 = (const float*)d_in[13];
    const float* W5 = (const float*)d_in[14]; const float* b5 = (const float*)d_in[15];
    const float* W6 = (const float*)d_in[16]; const float* b6 = (const float*)d_in[17];
    const float* W8 = (const float*)d_in[18]; const float* b8 = (const float*)d_in[19];
    const float* W9 = (const float*)d_in[20]; const float* b9 = (const float*)d_in[21];
    const float* W7 = (const float*)d_in[22]; const float* b7 = (const float*)d_in[23];
    const float* gamma = (const float*)d_in[24]; const float* beta = (const float*)d_in[25];
    float* out = (float*)d_out;

    int n = in_sizes[0] / F_DIM;   // 100000
    int e = in_sizes[1] / 2;       // 600000
    int g = in_sizes[3] / F_DIM;   // 1000
    int npg = n / g;               // 100

    int pool_smem = (npg * 256 + 256 + npg) * 4;

    static cudaStream_t sB = nullptr;
    static cudaEvent_t evFork = nullptr, evGraphReady = nullptr, evSideDone = nullptr;
    static bool init_done = false;
    if (!init_done) {
        cudaFuncSetAttribute(gemm_bf16x3, cudaFuncAttributeMaxDynamicSharedMemorySize, GEMM_SMEM);
        cudaFuncSetAttribute(gemm12, cudaFuncAttributeMaxDynamicSharedMemorySize, GEMM12_SMEM);
        cudaFuncSetAttribute(pool_kernel, cudaFuncAttributeMaxDynamicSharedMemorySize, 112 * 1024);
        cudaStreamCreateWithFlags(&sB, cudaStreamNonBlocking);
        cudaEventCreateWithFlags(&evFork, cudaEventDisableTiming);
        cudaEventCreateWithFlags(&evGraphReady, cudaEventDisableTiming);
        cudaEventCreateWithFlags(&evSideDone, cudaEventDisableTiming);
        init_done = true;
    }

    bf16 *featH = sym<bf16>(&d_featH), *featL = sym<bf16>(&d_featL);
    bf16 *TxH = sym<bf16>(&d_TxH), *TxL = sym<bf16>(&d_TxL);
    bf16 *H3H = sym<bf16>(&d_H3H), *H3L = sym<bf16>(&d_H3L);
    float* H4 = sym<float>(&d_H4);
    float *deg = sym<float>(&d_deg), *ew = sym<float>(&d_ew);
    int *cnt = sym<int>(&d_cnt), *elist = sym<int>(&d_elist);
    float *T2 = sym<float>(&d_T2), *X2 = sym<float>(&d_X2);
    float *hc = sym<float>(&d_hc), *mu = sym<float>(&d_mu), *rstd = sym<float>(&d_rstd);
    bf16 *W1tH = sym<bf16>(&d_W1tH), *W1tL = sym<bf16>(&d_W1tL);
    bf16 *W2tH = sym<bf16>(&d_W2tH), *W2tL = sym<bf16>(&d_W2tL);
    bf16 *WcH = sym<bf16>(&d_WcH), *WcL = sym<bf16>(&d_WcL);
    bf16 *W4tH = sym<bf16>(&d_W4tH), *W4tL = sym<bf16>(&d_W4tL);
    bf16 *Wc2H = sym<bf16>(&d_Wc2H), *Wc2L = sym<bf16>(&d_Wc2L);
    bf16 *W8tH = sym<bf16>(&d_W8tH), *W8tL = sym<bf16>(&d_W8tL);
    bf16 *W9tH = sym<bf16>(&d_W9tH), *W9tL = sym<bf16>(&d_W9tL);
    float *b3c = sym<float>(&d_b3c), *bx = sym<float>(&d_bx);
    bf16 *xLxH = sym<bf16>(&d_xLxH), *xLxL = sym<bf16>(&d_xLxL);
    bf16 *T1H = sym<bf16>(&d_T1H), *T1L = sym<bf16>(&d_T1L);

    const int* src = edge;
    const int* dst = edge + e;

    // ---- fork side stream from main (legacy) stream ----
    cudaEventRecord(evFork, 0);
    cudaStreamWaitEvent(sB, evFork, 0);

    // ---- side chain (stream sB): topology first, then weights, then graph MLPs ----
    zero_dc<<<(n + 255) / 256, 256, 0, sB>>>(deg, cnt, n);
    build_graph<<<(e + 255) / 256, 256, 0, sB>>>(src, dst, e, deg, cnt, elist);
    ew_kernel<<<(e + 255) / 256, 256, 0, sB>>>(src, dst, deg, ew, e);
    cudaEventRecord(evGraphReady, sB);     // ew/elist/cnt ready (gates props)
    split_contig<<<(g * 128 + 255) / 256, 256, 0, sB>>>(xLx, xLxH, xLxL, g * 128);
    transpose3<<<640, 256, 0, sB>>>(W4, W4tH, W4tL, W8, W8tH, W8tL, W9, W9tH, W9tL);
    build_wcombo<<<385, 256, 0, sB>>>(chebW, W3, chebb, b3, WcH, WcL, b3c);
    build_wc2<<<129, 256, 0, sB>>>(W5, W6, b5, b6, Wc2H, Wc2L, bx);
    launch_gemm_s(sB, xLxH, xLxL, 128, W8tH, W8tL, 128, b8,
                  nullptr, 0, T1H, T1L, 256, g, 256, 128, 1);
    launch_gemm_s(sB, T1H, T1L, 256, W9tH, W9tL, 256, b9,
                  T2, 256, nullptr, nullptr, 0, g, 256, 256, 1);
    launch_gemm_s(sB, xLxH, xLxL, 128, Wc2H, Wc2L, 128, bx,
                  X2, 256, nullptr, nullptr, 0, g, 256, 128, 1);
    cudaEventRecord(evSideDone, sB);       // T2, X2 ready (gates pool)

    // ---- main chain (stream 0) ----
    split_contig<<<(n * 128 + 255) / 256, 256>>>(features, featH, featL, n * 128);
    transpose_w12<<<128, 256>>>(W1, W1tH, W1tL, W2, W2tH, W2tL);
    gemm12<<<(n + 127) / 128, 256, GEMM12_SMEM>>>(featH, featL, W1tH, W1tL, b1,
                                                  W2tH, W2tL, b2, TxH, TxL, n);

    cudaStreamWaitEvent(0, evGraphReady, 0);
    prop_split1<<<(n * 32 + 255) / 256, 256>>>(TxH, TxL, ew, src, elist, cnt, n);
    prop_split2<<<(n * 32 + 255) / 256, 256>>>(TxH, TxL, ew, src, elist, cnt, n);

    launch_gemm_s(0, TxH, TxL, 384, WcH, WcL, 384, b3c,
                  nullptr, 0, H3H, H3L, 256, n, 256, 384, 1);
    launch_gemm_s(0, H3H, H3L, 256, W4tH, W4tL, 256, b4,
                  H4, 256, nullptr, nullptr, 0, n, 256, 256, 1);

    cudaStreamWaitEvent(0, evSideDone, 0);
    pool_kernel<<<g, 256, pool_smem>>>(H4, T2, X2, hc, npg);
    bn_stats<<<C2, 256>>>(hc, mu, rstd, g);
    bn_final<<<g, 256>>>(hc, mu, rstd, gamma, beta, W7, b7, out);
}

// round 17
// speedup vs baseline: 1.1795x; 1.0455x over previous
#include <cuda_runtime.h>
#include <cuda_bf16.h>
#include <cstdint>
#include <math.h>

#define N_NODES 100000
#define F_DIM   128
#define E_EDGES 600000
#define G_GRAPHS 1000
#define HDIM    256
#define C2      (2*HDIM)
#define ECAP    96

typedef __nv_bfloat16 bf16;

// ---------------- scratch (static device memory; no allocs) ----------------
__device__ bf16  d_TxH [(size_t)N_NODES * 384];   // [Tx0|Tx1|Tx2] hi
__device__ bf16  d_TxL [(size_t)N_NODES * 384];   // [Tx0|Tx1|Tx2] lo
__device__ bf16  d_H3H [(size_t)N_NODES * 256];
__device__ bf16  d_H3L [(size_t)N_NODES * 256];
__device__ float d_H4  [(size_t)N_NODES * 256];
__device__ float d_deg [N_NODES];
__device__ float d_ew  [E_EDGES];
__device__ int   d_cnt [N_NODES];
__device__ int   d_elist[(size_t)N_NODES * ECAP];
__device__ float d_T2  [G_GRAPHS * HDIM];
__device__ float d_X2  [G_GRAPHS * HDIM];
__device__ float d_hc  [G_GRAPHS * C2];
__device__ float d_mu  [C2];
__device__ float d_rstd[C2];
// bf16 hi/lo transposed weights [N,K]
__device__ bf16 d_W1tH[128*128], d_W1tL[128*128];
__device__ bf16 d_W2tH[128*128], d_W2tL[128*128];
__device__ bf16 d_WcH [256*384], d_WcL [256*384];   // (Wbig@W3)^T
__device__ bf16 d_W4tH[256*256], d_W4tL[256*256];
__device__ bf16 d_Wc2H[256*128], d_Wc2L[256*128];   // (W5@W6)^T
__device__ bf16 d_W8tH[256*128], d_W8tL[256*128];
__device__ bf16 d_W9tH[256*256], d_W9tL[256*256];
__device__ float d_b3c [256];
__device__ float d_bx  [256];
// graph-side activations
__device__ bf16 d_xLxH[G_GRAPHS*128], d_xLxL[G_GRAPHS*128];
__device__ bf16 d_T1H [G_GRAPHS*256], d_T1L [G_GRAPHS*256];

// ---------------- helpers ----------------
__device__ __forceinline__ uint32_t smem_to_u32(const void* p) {
    uint32_t a;
    asm("{ .reg .u64 t; cvta.to.shared.u64 t, %1; cvt.u32.u64 %0, t; }" : "=r"(a) : "l"(p));
    return a;
}
__device__ __forceinline__ void split1(float v, bf16& h, bf16& l) {
    h = __float2bfloat16(v);
    l = __float2bfloat16(v - __bfloat162float(h));
}
__device__ __forceinline__ uint32_t pack2h(float a, float b) {
    __nv_bfloat162 t = __floats2bfloat162_rn(a, b);
    return *reinterpret_cast<uint32_t*>(&t);
}
__device__ __forceinline__ uint32_t pack2l(float a, float b) {
    float ra = a - __bfloat162float(__float2bfloat16(a));
    float rb = b - __bfloat162float(__float2bfloat16(b));
    __nv_bfloat162 t = __floats2bfloat162_rn(ra, rb);
    return *reinterpret_cast<uint32_t*>(&t);
}
// reconstruct 2 fp32 from packed hi/lo bf16x2
__device__ __forceinline__ float2 rec2(uint32_t h, uint32_t l) {
    __nv_bfloat162 hh = *reinterpret_cast<__nv_bfloat162*>(&h);
    __nv_bfloat162 ll = *reinterpret_cast<__nv_bfloat162*>(&l);
    return make_float2(__bfloat162float(hh.x) + __bfloat162float(ll.x),
                       __bfloat162float(hh.y) + __bfloat162float(ll.y));
}

#define LDMX4(r, addr)                                                          \
    asm volatile("ldmatrix.sync.aligned.m8n8.x4.shared.b16 {%0,%1,%2,%3}, [%4];"\
        : "=r"((r)[0]), "=r"((r)[1]), "=r"((r)[2]), "=r"((r)[3]) : "r"(addr))

#define CP16(dst, src, sz)                                                      \
    asm volatile("cp.async.cg.shared.global [%0], [%1], 16, %2;"                \
        :: "r"(dst), "l"(src), "r"(sz))

#define MMA4(d, a, b0v, b1v)                                                    \
    asm("mma.sync.aligned.m16n8k16.row.col.f32.bf16.bf16.f32 "                  \
        "{%0,%1,%2,%3}, {%4,%5,%6,%7}, {%8,%9}, {%0,%1,%2,%3};"                 \
        : "+f"((d)[0]), "+f"((d)[1]), "+f"((d)[2]), "+f"((d)[3])                \
        : "r"((a)[0]), "r"((a)[1]), "r"((a)[2]), "r"((a)[3]), "r"(b0v), "r"(b1v))

// ---------------- GEMM: C = act(A @ Bt^T + bias), bf16x3 split operands ------
__global__ __launch_bounds__(256, 2)
void gemm_bf16x3(const bf16* __restrict__ Ahi, const bf16* __restrict__ Alo, int lda,
                 const bf16* __restrict__ Bhi, const bf16* __restrict__ Blo, int ldb,
                 const float* __restrict__ bias,
                 float* __restrict__ Cf, int ldcf,
                 bf16* __restrict__ Chi, bf16* __restrict__ Clo, int ldch,
                 int M, int K, int act) {
    extern __shared__ char smem[];
    const uint32_t sbase = smem_to_u32(smem);
    const int tid = threadIdx.x, lane = tid & 31, wid = tid >> 5;
    const int wm = wid >> 2, wn = wid & 3;
    const int bm = blockIdx.y * 128, bn = blockIdx.x * 128;
    const int nch = K >> 5;            // always even

    float acc[4][4][4];
#pragma unroll
    for (int i = 0; i < 4; i++)
#pragma unroll
        for (int j = 0; j < 4; j++)
#pragma unroll
            for (int r = 0; r < 4; r++) acc[i][j][r] = 0.f;

    const int r0 = tid >> 2, ch = tid & 3;
    const int r1 = r0 + 64;
    const uint32_t sz0 = (bm + r0 < M) ? 16u : 0u;
    const uint32_t sz1 = (bm + r1 < M) ? 16u : 0u;
    const char* pA0h = (const char*)(Ahi + (size_t)(bm + r0) * lda + ch * 8);
    const char* pA0l = (const char*)(Alo + (size_t)(bm + r0) * lda + ch * 8);
    const char* pA1h = (const char*)(Ahi + (size_t)(bm + r1) * lda + ch * 8);
    const char* pA1l = (const char*)(Alo + (size_t)(bm + r1) * lda + ch * 8);
    const char* pB0h = (const char*)(Bhi + (size_t)(bn + r0) * ldb + ch * 8);
    const char* pB0l = (const char*)(Blo + (size_t)(bn + r0) * ldb + ch * 8);
    const char* pB1h = (const char*)(Bhi + (size_t)(bn + r1) * ldb + ch * 8);
    const char* pB1l = (const char*)(Blo + (size_t)(bn + r1) * ldb + ch * 8);
    const uint32_t dA0 = sbase + r0 * 80 + ch * 16;
    const uint32_t dA1 = dA0 + 64 * 80;
    const uint32_t dB0 = dA0 + 20480;
    const uint32_t dB1 = dA1 + 20480;

    auto stage_load = [&](int c, uint32_t so) {
        const uint32_t ko = (uint32_t)c * 64u;
        CP16(dA0 + so,         pA0h + ko, sz0);
        CP16(dA0 + so + 10240, pA0l + ko, sz0);
        CP16(dA1 + so,         pA1h + ko, sz1);
        CP16(dA1 + so + 10240, pA1l + ko, sz1);
        CP16(dB0 + so,         pB0h + ko, 16u);
        CP16(dB0 + so + 10240, pB0l + ko, 16u);
        CP16(dB1 + so,         pB1h + ko, 16u);
        CP16(dB1 + so + 10240, pB1l + ko, 16u);
    };

    stage_load(0, 0);
    asm volatile("cp.async.commit_group;");
    stage_load(1, 40960);
    asm volatile("cp.async.commit_group;");

    const int rsub = ((lane >> 3) & 1) * 8 + (lane & 7);
    const uint32_t csel = (uint32_t)((lane >> 4) << 4);
    const uint32_t aBase = sbase + (uint32_t)(wm * 64 + rsub) * 80 + csel;
    const uint32_t bBase = sbase + 20480 + (uint32_t)(wn * 32 + rsub) * 80 + csel;

    auto chunk = [&](int c, uint32_t so) {
        asm volatile("cp.async.wait_group 1;");
        __syncthreads();
#pragma unroll
        for (int kt = 0; kt < 2; kt++) {
            const uint32_t ko = so + (uint32_t)(kt * 32);
            uint32_t bh[2][4], bl[2][4];
#pragma unroll
            for (int np = 0; np < 2; np++) {
                LDMX4(bh[np], bBase + ko + np * 1280);
                LDMX4(bl[np], bBase + ko + np * 1280 + 10240);
            }
#pragma unroll
            for (int i = 0; i < 4; i++) {
                uint32_t ah[4], al[4];
                LDMX4(ah, aBase + ko + i * 1280);
                LDMX4(al, aBase + ko + i * 1280 + 10240);
#pragma unroll
                for (int j = 0; j < 4; j++) {
                    const int np = j >> 1, o = j & 1;
                    MMA4(acc[i][j], ah, bh[np][o], bh[np][2 + o]);
                    MMA4(acc[i][j], ah, bl[np][o], bl[np][2 + o]);
                    MMA4(acc[i][j], al, bh[np][o], bh[np][2 + o]);
                }
            }
        }
        __syncthreads();
        if (c + 2 < nch) stage_load(c + 2, so);
        asm volatile("cp.async.commit_group;");
    };

    for (int c = 0; c < nch; c += 2) {
        chunk(c, 0);
        chunk(c + 1, 40960);
    }

    const int g = lane >> 2, tg = lane & 3;
#pragma unroll
    for (int i = 0; i < 4; i++) {
        const int row0 = bm + wm * 64 + i * 16 + g;
#pragma unroll
        for (int j = 0; j < 4; j++) {
            const int col = bn + wn * 32 + j * 8 + tg * 2;
            const float b0 = bias[col], b1 = bias[col + 1];
#pragma unroll
            for (int h = 0; h < 2; h++) {
                const int row = row0 + h * 8;
                if (row >= M) continue;
                float v0 = acc[i][j][h * 2 + 0] + b0;
                float v1 = acc[i][j][h * 2 + 1] + b1;
                if (act) {
                    v0 = v0 > 0.f ? v0 : 0.01f * v0;
                    v1 = v1 > 0.f ? v1 : 0.01f * v1;
                }
                if (Cf) {
                    float2 fv = make_float2(v0, v1);
                    *reinterpret_cast<float2*>(&Cf[(size_t)row * ldcf + col]) = fv;
                }
                if (Chi) {
                    *reinterpret_cast<uint32_t*>(&Chi[(size_t)row * ldch + col]) = pack2h(v0, v1);
                    *reinterpret_cast<uint32_t*>(&Clo[(size_t)row * ldch + col]) = pack2l(v0, v1);
                }
            }
        }
    }
}

// ---------------- fused W1+W2 GEMM (fp32 features converted inline) ----------
__global__ __launch_bounds__(256, 2)
void gemm12(const float* __restrict__ feat,
            const bf16* __restrict__ W1H, const bf16* __restrict__ W1L,
            const float* __restrict__ b1,
            const bf16* __restrict__ W2H, const bf16* __restrict__ W2L,
            const float* __restrict__ b2,
            bf16* __restrict__ TxH, bf16* __restrict__ TxL,
            int M) {
    extern __shared__ char smem[];
    const uint32_t sbase = smem_to_u32(smem);
    const int tid = threadIdx.x, lane = tid & 31, wid = tid >> 5;
    const int wm = wid >> 2, wn = wid & 3;
    const int bm = blockIdx.x * 128;

    float acc[4][4][4];
#pragma unroll
    for (int i = 0; i < 4; i++)
#pragma unroll
        for (int j = 0; j < 4; j++)
#pragma unroll
            for (int r = 0; r < 4; r++) acc[i][j][r] = 0.f;

    const int r0 = tid >> 2, ch = tid & 3;
    const int r1 = r0 + 64;
    const bool in0 = (bm + r0 < M);
    const bool in1 = (bm + r1 < M);
    const uint32_t oA0 = (uint32_t)(r0 * 80 + ch * 16);   // offsets rel. to smem base
    const uint32_t oA1 = oA0 + 64 * 80;
    const uint32_t dB0 = sbase + oA0 + 20480;
    const uint32_t dB1 = sbase + oA1 + 20480;

    // ---- phase 1: feat(fp32) @ W1; A converted inline, B via cp.async ----
    {
        const float* f0 = feat + (size_t)(bm + r0) * 128 + ch * 8;
        const float* f1 = feat + (size_t)(bm + r1) * 128 + ch * 8;
        const char* pB0h = (const char*)(W1H + (size_t)r0 * 128 + ch * 8);
        const char* pB0l = (const char*)(W1L + (size_t)r0 * 128 + ch * 8);
        const char* pB1h = (const char*)(W1H + (size_t)r1 * 128 + ch * 8);
        const char* pB1l = (const char*)(W1L + (size_t)r1 * 128 + ch * 8);

        float4 a0[2], a1[2];
        auto ldgA = [&](int c) {
            if (in0) {
                a0[0] = *reinterpret_cast<const float4*>(f0 + c * 32);
                a0[1] = *reinterpret_cast<const float4*>(f0 + c * 32 + 4);
            } else {
                a0[0] = make_float4(0.f, 0.f, 0.f, 0.f);
                a0[1] = make_float4(0.f, 0.f, 0.f, 0.f);
            }
            if (in1) {
                a1[0] = *reinterpret_cast<const float4*>(f1 + c * 32);
                a1[1] = *reinterpret_cast<const float4*>(f1 + c * 32 + 4);
            } else {
                a1[0] = make_float4(0.f, 0.f, 0.f, 0.f);
                a1[1] = make_float4(0.f, 0.f, 0.f, 0.f);
            }
        };
        auto stsA = [&](uint32_t so) {
            uint4 h0 = make_uint4(pack2h(a0[0].x, a0[0].y), pack2h(a0[0].z, a0[0].w),
                                  pack2h(a0[1].x, a0[1].y), pack2h(a0[1].z, a0[1].w));
            uint4 l0 = make_uint4(pack2l(a0[0].x, a0[0].y), pack2l(a0[0].z, a0[0].w),
                                  pack2l(a0[1].x, a0[1].y), pack2l(a0[1].z, a0[1].w));
            uint4 h1 = make_uint4(pack2h(a1[0].x, a1[0].y), pack2h(a1[0].z, a1[0].w),
                                  pack2h(a1[1].x, a1[1].y), pack2h(a1[1].z, a1[1].w));
            uint4 l1 = make_uint4(pack2l(a1[0].x, a1[0].y), pack2l(a1[0].z, a1[0].w),
                                  pack2l(a1[1].x, a1[1].y), pack2l(a1[1].z, a1[1].w));
            *reinterpret_cast<uint4*>(smem + oA0 + so)         = h0;
            *reinterpret_cast<uint4*>(smem + oA0 + so + 10240) = l0;
            *reinterpret_cast<uint4*>(smem + oA1 + so)         = h1;
            *reinterpret_cast<uint4*>(smem + oA1 + so + 10240) = l1;
        };
        auto cpB = [&](int c, uint32_t so) {
            const uint32_t ko = (uint32_t)c * 64u;
            CP16(dB0 + so,         pB0h + ko, 16u);
            CP16(dB0 + so + 10240, pB0l + ko, 16u);
            CP16(dB1 + so,         pB1h + ko, 16u);
            CP16(dB1 + so + 10240, pB1l + ko, 16u);
        };

        cpB(0, 0);
        asm volatile("cp.async.commit_group;");
        cpB(1, 40960);
        asm volatile("cp.async.commit_group;");
        ldgA(0); stsA(0);
        ldgA(1); stsA(40960);

        const int rsub = ((lane >> 3) & 1) * 8 + (lane & 7);
        const uint32_t csel = (uint32_t)((lane >> 4) << 4);
        const uint32_t aBase = sbase + (uint32_t)(wm * 64 + rsub) * 80 + csel;
        const uint32_t bBase = sbase + 20480 + (uint32_t)(wn * 32 + rsub) * 80 + csel;

        auto chunk = [&](int c, uint32_t so) {
            asm volatile("cp.async.wait_group 1;");
            __syncthreads();
            if (c + 2 < 4) ldgA(c + 2);     // prefetch next A (fp32) into regs
#pragma unroll
            for (int kt = 0; kt < 2; kt++) {
                const uint32_t ko = so + (uint32_t)(kt * 32);
                uint32_t bh[2][4], bl[2][4];
#pragma unroll
                for (int np = 0; np < 2; np++) {
                    LDMX4(bh[np], bBase + ko + np * 1280);
                    LDMX4(bl[np], bBase + ko + np * 1280 + 10240);
                }
#pragma unroll
                for (int i = 0; i < 4; i++) {
                    uint32_t ah[4], al[4];
                    LDMX4(ah, aBase + ko + i * 1280);
                    LDMX4(al, aBase + ko + i * 1280 + 10240);
#pragma unroll
                    for (int j = 0; j < 4; j++) {
                        const int np = j >> 1, o = j & 1;
                        MMA4(acc[i][j], ah, bh[np][o], bh[np][2 + o]);
                        MMA4(acc[i][j], ah, bl[np][o], bl[np][2 + o]);
                        MMA4(acc[i][j], al, bh[np][o], bh[np][2 + o]);
                    }
                }
            }
            __syncthreads();
            if (c + 2 < 4) { stsA(so); cpB(c + 2, so); }
            asm volatile("cp.async.commit_group;");
        };

        chunk(0, 0);
        chunk(1, 40960);
        chunk(2, 0);
        chunk(3, 40960);
    }

    // ---- hand-off: bias+leaky, store H1 hi/lo into 4 chunk-buffers ----
    const int g = lane >> 2, tg = lane & 3;
#pragma unroll
    for (int i = 0; i < 4; i++) {
        const int crow = wm * 64 + i * 16 + g;
#pragma unroll
        for (int j = 0; j < 4; j++) {
            const int col = wn * 32 + j * 8 + tg * 2;
            const float b0 = b1[col], b1v = b1[col + 1];
            const int c2 = col >> 5, kin = col & 31;
            const uint32_t base = sbase + (uint32_t)c2 * 20480 + kin * 2;
#pragma unroll
            for (int h = 0; h < 2; h++) {
                float v0 = acc[i][j][h * 2 + 0] + b0;
                float v1 = acc[i][j][h * 2 + 1] + b1v;
                v0 = v0 > 0.f ? v0 : 0.01f * v0;
                v1 = v1 > 0.f ? v1 : 0.01f * v1;
                const uint32_t a = base + (uint32_t)(crow + h * 8) * 80;
                *reinterpret_cast<uint32_t*>(smem + (a - sbase))         = pack2h(v0, v1);
                *reinterpret_cast<uint32_t*>(smem + (a - sbase) + 10240) = pack2l(v0, v1);
                acc[i][j][h * 2 + 0] = 0.f;
                acc[i][j][h * 2 + 1] = 0.f;
            }
        }
    }
    __syncthreads();

    // ---- phase 2: H1 @ W2, B single-stage at +81920 ----
    {
        const char* pW0h = (const char*)(W2H + (size_t)r0 * 128 + ch * 8);
        const char* pW0l = (const char*)(W2L + (size_t)r0 * 128 + ch * 8);
        const char* pW1h = (const char*)(W2H + (size_t)r1 * 128 + ch * 8);
        const char* pW1l = (const char*)(W2L + (size_t)r1 * 128 + ch * 8);
        const uint32_t eB0 = sbase + oA0 + 81920;
        const uint32_t eB1 = eB0 + 64 * 80;

        const int rsub = ((lane >> 3) & 1) * 8 + (lane & 7);
        const uint32_t csel = (uint32_t)((lane >> 4) << 4);
        const uint32_t aB2 = sbase + (uint32_t)(wm * 64 + rsub) * 80 + csel;
        const uint32_t bB2 = sbase + 81920 + (uint32_t)(wn * 32 + rsub) * 80 + csel;

        for (int c2 = 0; c2 < 4; c2++) {
            const uint32_t ko = (uint32_t)c2 * 64u;
            CP16(eB0,         pW0h + ko, 16u);
            CP16(eB0 + 10240, pW0l + ko, 16u);
            CP16(eB1,         pW1h + ko, 16u);
            CP16(eB1 + 10240, pW1l + ko, 16u);
            asm volatile("cp.async.commit_group;");
            asm volatile("cp.async.wait_group 0;");
            __syncthreads();
            const uint32_t aC = aB2 + (uint32_t)c2 * 20480;
#pragma unroll
            for (int kt = 0; kt < 2; kt++) {
                const uint32_t ko2 = (uint32_t)(kt * 32);
                uint32_t bh[2][4], bl[2][4];
#pragma unroll
                for (int np = 0; np < 2; np++) {
                    LDMX4(bh[np], bB2 + ko2 + np * 1280);
                    LDMX4(bl[np], bB2 + ko2 + np * 1280 + 10240);
                }
#pragma unroll
                for (int i = 0; i < 4; i++) {
                    uint32_t ah[4], al[4];
                    LDMX4(ah, aC + ko2 + i * 1280);
                    LDMX4(al, aC + ko2 + i * 1280 + 10240);
#pragma unroll
                    for (int j = 0; j < 4; j++) {
                        const int np = j >> 1, o = j & 1;
                        MMA4(acc[i][j], ah, bh[np][o], bh[np][2 + o]);
                        MMA4(acc[i][j], ah, bl[np][o], bl[np][2 + o]);
                        MMA4(acc[i][j], al, bh[np][o], bh[np][2 + o]);
                    }
                }
            }
            __syncthreads();
        }
    }

#pragma unroll
    for (int i = 0; i < 4; i++) {
        const int row0 = bm + wm * 64 + i * 16 + g;
#pragma unroll
        for (int j = 0; j < 4; j++) {
            const int col = wn * 32 + j * 8 + tg * 2;
            const float c0 = b2[col], c1 = b2[col + 1];
#pragma unroll
            for (int h = 0; h < 2; h++) {
                const int row = row0 + h * 8;
                if (row >= M) continue;
                float v0 = acc[i][j][h * 2 + 0] + c0;
                float v1 = acc[i][j][h * 2 + 1] + c1;
                v0 = v0 > 0.f ? v0 : 0.01f * v0;
                v1 = v1 > 0.f ? v1 : 0.01f * v1;
                *reinterpret_cast<uint32_t*>(&TxH[(size_t)row * 384 + col]) = pack2h(v0, v1);
                *reinterpret_cast<uint32_t*>(&TxL[(size_t)row * 384 + col]) = pack2l(v0, v1);
            }
        }
    }
}

// ---------------- weight-combination builders ----------------
__global__ void build_wcombo(const float* __restrict__ chebW, const float* __restrict__ W3,
                             const float* __restrict__ chebb, const float* __restrict__ b3,
                             bf16* __restrict__ WcH, bf16* __restrict__ WcL,
                             float* __restrict__ b3c) {
    int c = threadIdx.x;
    if (blockIdx.x == 384) {
        float acc = b3[c];
        for (int n = 0; n < 512; n++) acc += chebb[n] * W3[n * 256 + c];
        b3c[c] = acc;
        return;
    }
    __shared__ float wrow[512];
    int k = blockIdx.x;
    int kk = k >> 7, i = k & 127;
    for (int idx = c; idx < 512; idx += 256) {
        int w = idx >> 7, j = idx & 127;
        wrow[idx] = chebW[(((w * 3) + kk) * 128 + i) * 128 + j];
    }
    __syncthreads();
    float acc = 0.f;
#pragma unroll 8
    for (int j = 0; j < 512; j++) acc += wrow[j] * W3[j * 256 + c];
    bf16 h, l; split1(acc, h, l);
    WcH[c * 384 + k] = h; WcL[c * 384 + k] = l;
}

__global__ void build_wc2(const float* __restrict__ W5, const float* __restrict__ W6,
                          const float* __restrict__ b5, const float* __restrict__ b6,
                          bf16* __restrict__ Wc2H, bf16* __restrict__ Wc2L,
                          float* __restrict__ bx) {
    int c = threadIdx.x;
    if (blockIdx.x == 128) {
        float acc = b6[c];
        for (int j = 0; j < 256; j++) acc += b5[j] * W6[j * 256 + c];
        bx[c] = acc;
        return;
    }
    __shared__ float wrow[256];
    int k = blockIdx.x;
    wrow[c] = W5[k * 256 + c];
    __syncthreads();
    float acc = 0.f;
#pragma unroll 8
    for (int j = 0; j < 256; j++) acc += wrow[j] * W6[j * 256 + c];
    bf16 h, l; split1(acc, h, l);
    Wc2H[c * 128 + k] = h; Wc2L[c * 128 + k] = l;
}

// ---------------- prep / convert kernels ----------------
__global__ void zero_dc(float* deg, int* cnt, int n) {
    int i = blockIdx.x * 256 + threadIdx.x;
    if (i < n) { deg[i] = 0.f; cnt[i] = 0; }
}
__global__ void split_contig(const float* __restrict__ s, bf16* __restrict__ h,
                             bf16* __restrict__ l, int n) {
    int i = blockIdx.x * 256 + threadIdx.x;
    if (i < n) { bf16 hh, ll; split1(s[i], hh, ll); h[i] = hh; l[i] = ll; }
}
__global__ void transpose_w12(const float* __restrict__ W1, bf16* __restrict__ W1tH, bf16* __restrict__ W1tL,
                              const float* __restrict__ W2, bf16* __restrict__ W2tH, bf16* __restrict__ W2tL) {
    int idx = blockIdx.x * 256 + threadIdx.x;
    if (idx >= 32768) return;
    const float* W = (idx < 16384) ? W1 : W2;
    bf16* Th = (idx < 16384) ? W1tH : W2tH;
    bf16* Tl = (idx < 16384) ? W1tL : W2tL;
    int t = idx & 16383;
    int k = t >> 7, n = t & 127;
    bf16 h, l; split1(W[t], h, l);
    Th[n * 128 + k] = h; Tl[n * 128 + k] = l;
}
__global__ void transpose3(const float* __restrict__ W4, bf16* __restrict__ W4tH, bf16* __restrict__ W4tL,
                           const float* __restrict__ W8, bf16* __restrict__ W8tH, bf16* __restrict__ W8tL,
                           const float* __restrict__ W9, bf16* __restrict__ W9tH, bf16* __restrict__ W9tL) {
    int idx = blockIdx.x * 256 + threadIdx.x;
    const float* W; bf16 *Th, *Tl; int K, t;
    if (idx < 65536)       { W = W4; Th = W4tH; Tl = W4tL; K = 256; t = idx; }
    else if (idx < 98304)  { W = W8; Th = W8tH; Tl = W8tL; K = 128; t = idx - 65536; }
    else if (idx < 163840) { W = W9; Th = W9tH; Tl = W9tL; K = 256; t = idx - 98304; }
    else return;
    int k = t / 256, n = t % 256;
    bf16 h, l; split1(W[t], h, l);
    Th[n * K + k] = h; Tl[n * K + k] = l;
}

// ---------------- graph structure ----------------
__global__ void build_graph(const int* __restrict__ src, const int* __restrict__ dst, int e,
                            float* __restrict__ deg, int* __restrict__ cnt,
                            int* __restrict__ elist) {
    int i = blockIdx.x * 256 + threadIdx.x;
    if (i >= e) return;
    atomicAdd(&deg[src[i]], 1.0f);
    int d = dst[i];
    int p = atomicAdd(&cnt[d], 1);
    if (p < ECAP) elist[(size_t)d * ECAP + p] = i;
}
__global__ void ew_kernel(const int* __restrict__ src, const int* __restrict__ dst,
                          const float* __restrict__ deg, float* __restrict__ ew, int e) {
    int i = blockIdx.x * 256 + threadIdx.x;
    if (i >= e) return;
    float ds = rsqrtf(fmaxf(deg[src[i]], 1.f));
    float dv = deg[dst[i]];
    float dd = (dv > 0.f) ? rsqrtf(fmaxf(dv, 1.f)) : 0.f;
    ew[i] = -(ds * dd);
}

// prop #1: Tx1 = P(Tx0). Reads hi/lo splits (cols 0-127), reconstructs fp32,
// writes hi/lo of Tx1 (cols 128-255). Warp per node, no atomics.
__global__ void prop_split1(bf16* __restrict__ TxH, bf16* __restrict__ TxL,
                            const float* __restrict__ ew,
                            const int* __restrict__ src, const int* __restrict__ elist,
                            const int* __restrict__ cnt, int n) {
    int v = (blockIdx.x * 256 + threadIdx.x) >> 5;
    int lane = threadIdx.x & 31;
    if (v >= n) return;
    int c = cnt[v];
    if (c > ECAP) c = ECAP;
    float4 acc = make_float4(0.f, 0.f, 0.f, 0.f);
    const int* el = &elist[(size_t)v * ECAP];
    for (int i = 0; i < c; i++) {
        int eid = el[i];
        int s = src[eid];
        float w = ew[eid];
        size_t p = (size_t)s * 384 + lane * 4;
        uint2 h = *reinterpret_cast<const uint2*>(&TxH[p]);
        uint2 l = *reinterpret_cast<const uint2*>(&TxL[p]);
        float2 a = rec2(h.x, l.x), b = rec2(h.y, l.y);
        acc.x += w * a.x; acc.y += w * a.y; acc.z += w * b.x; acc.w += w * b.y;
    }
    size_t o = (size_t)v * 384 + 128 + lane * 4;
    *reinterpret_cast<uint32_t*>(&TxH[o])     = pack2h(acc.x, acc.y);
    *reinterpret_cast<uint32_t*>(&TxH[o + 2]) = pack2h(acc.z, acc.w);
    *reinterpret_cast<uint32_t*>(&TxL[o])     = pack2l(acc.x, acc.y);
    *reinterpret_cast<uint32_t*>(&TxL[o + 2]) = pack2l(acc.z, acc.w);
}

// prop #2: Tx2 = 2*P(Tx1) - Tx0. Reads Tx1 splits (cols 128-255) of neighbors
// and Tx0 splits (cols 0-127) of v; writes hi/lo of Tx2 (cols 256-383).
__global__ void prop_split2(bf16* __restrict__ TxH, bf16* __restrict__ TxL,
                            const float* __restrict__ ew,
                            const int* __restrict__ src, const int* __restrict__ elist,
                            const int* __restrict__ cnt, int n) {
    int v = (blockIdx.x * 256 + threadIdx.x) >> 5;
    int lane = threadIdx.x & 31;
    if (v >= n) return;
    int c = cnt[v];
    if (c > ECAP) c = ECAP;
    float4 acc = make_float4(0.f, 0.f, 0.f, 0.f);
    const int* el = &elist[(size_t)v * ECAP];
    for (int i = 0; i < c; i++) {
        int eid = el[i];
        int s = src[eid];
        float w = ew[eid];
        size_t p = (size_t)s * 384 + 128 + lane * 4;
        uint2 h = *reinterpret_cast<const uint2*>(&TxH[p]);
        uint2 l = *reinterpret_cast<const uint2*>(&TxL[p]);
        float2 a = rec2(h.x, l.x), b = rec2(h.y, l.y);
        acc.x += w * a.x; acc.y += w * a.y; acc.z += w * b.x; acc.w += w * b.y;
    }
    size_t q = (size_t)v * 384 + lane * 4;
    uint2 h0 = *reinterpret_cast<const uint2*>(&TxH[q]);
    uint2 l0 = *reinterpret_cast<const uint2*>(&TxL[q]);
    float2 t0a = rec2(h0.x, l0.x), t0b = rec2(h0.y, l0.y);
    acc.x = 2.f * acc.x - t0a.x; acc.y = 2.f * acc.y - t0a.y;
    acc.z = 2.f * acc.z - t0b.x; acc.w = 2.f * acc.w - t0b.y;
    size_t o = (size_t)v * 384 + 256 + lane * 4;
    *reinterpret_cast<uint32_t*>(&TxH[o])     = pack2h(acc.x, acc.y);
    *reinterpret_cast<uint32_t*>(&TxH[o + 2]) = pack2h(acc.z, acc.w);
    *reinterpret_cast<uint32_t*>(&TxL[o])     = pack2l(acc.x, acc.y);
    *reinterpret_cast<uint32_t*>(&TxL[o + 2]) = pack2l(acc.z, acc.w);
}

// ---------------- fused attention pooling + concat ----------------
__global__ void pool_kernel(const float* __restrict__ H4, const float* __restrict__ T2,
                            const float* __restrict__ X2, float* __restrict__ hc, int npg) {
    extern __shared__ float sm[];
    float* sH = sm;
    float* sT = sm + npg * 256;
    float* sS = sT + 256;
    int g = blockIdx.x, tid = threadIdx.x;
    const float* Hg = H4 + (size_t)g * npg * 256;
    for (int i = tid; i < npg * 256; i += 256) sH[i] = Hg[i];
    sT[tid] = T2[g * 256 + tid];
    __syncthreads();
    int wid = tid >> 5, lane = tid & 31;
    for (int v = wid; v < npg; v += 8) {
        float s = 0.f;
#pragma unroll
        for (int k = 0; k < 8; k++) s += sH[v * 256 + lane + 32 * k] * sT[lane + 32 * k];
#pragma unroll
        for (int o = 16; o > 0; o >>= 1) s += __shfl_xor_sync(0xffffffffu, s, o);
        if (lane == 0) sS[v] = s;
    }
    __syncthreads();
    float acc = 0.f;
    for (int v = 0; v < npg; v++) acc += sH[v * 256 + tid] * sS[v];
    hc[g * C2 + tid] = acc / (float)npg;
    hc[g * C2 + 256 + tid] = X2[g * 256 + tid];
}

// ---------------- BN / classifier ----------------
__global__ void bn_stats(const float* __restrict__ hc, float* __restrict__ mu,
                         float* __restrict__ rstd, int g) {
    int c = blockIdx.x;
    int tid = threadIdx.x;
    __shared__ float red[256];
    float s = 0.f;
    for (int i = tid; i < g; i += 256) s += hc[i * C2 + c];
    red[tid] = s;
    __syncthreads();
    for (int o = 128; o > 0; o >>= 1) {
        if (tid < o) red[tid] += red[tid + o];
        __syncthreads();
    }
    float m = red[0] / (float)g;
    __syncthreads();
    float sq = 0.f;
    for (int i = tid; i < g; i += 256) {
        float d = hc[i * C2 + c] - m;
        sq += d * d;
    }
    red[tid] = sq;
    __syncthreads();
    for (int o = 128; o > 0; o >>= 1) {
        if (tid < o) red[tid] += red[tid + o];
        __syncthreads();
    }
    if (tid == 0) {
        mu[c] = m;
        rstd[c] = rsqrtf(red[0] / (float)g + 1e-5f);
    }
}

__global__ void bn_final(const float* __restrict__ hc, const float* __restrict__ mu,
                         const float* __restrict__ rstd, const float* __restrict__ gamma,
                         const float* __restrict__ beta, const float* __restrict__ W7,
                         const float* __restrict__ b7, float* __restrict__ out) {
    int g = blockIdx.x;
    int tid = threadIdx.x;
    __shared__ float r0[256], r1[256];
    float s0 = 0.f, s1 = 0.f;
    for (int c = tid; c < C2; c += 256) {
        float v = (hc[g * C2 + c] - mu[c]) * rstd[c] * gamma[c] + beta[c];
        s0 += v * W7[c * 2 + 0];
        s1 += v * W7[c * 2 + 1];
    }
    r0[tid] = s0; r1[tid] = s1;
    __syncthreads();
    for (int o = 128; o > 0; o >>= 1) {
        if (tid < o) { r0[tid] += r0[tid + o]; r1[tid] += r1[tid + o]; }
        __syncthreads();
    }
    if (tid == 0) {
        out[g * 2 + 0] = r0[0] + b7[0];
        out[g * 2 + 1] = r1[0] + b7[1];
    }
}

// ---------------- launch ----------------
#define GEMM_SMEM   81920
#define GEMM12_SMEM 102400

static void launch_gemm_s(cudaStream_t s,
                          const bf16* Ah, const bf16* Al, int lda,
                          const bf16* Bh, const bf16* Bl, int ldb, const float* bias,
                          float* Cf, int ldcf, bf16* Ch, bf16* Cl, int ldch,
                          int M, int N, int K, int act) {
    dim3 grid(N / 128, (M + 127) / 128);
    gemm_bf16x3<<<grid, 256, GEMM_SMEM, s>>>(Ah, Al, lda, Bh, Bl, ldb, bias,
                                             Cf, ldcf, Ch, Cl, ldch, M, K, act);
}

template <typename T>
static T* sym(const void* s) { void* p; cudaGetSymbolAddress(&p, s); return (T*)p; }

extern "C" void kernel_launch(void* const* d_in, const int* in_sizes, int n_in,
                              void* d_out, int out_size) {
    const float* features = (const float*)d_in[0];
    const int*   edge     = (const int*)d_in[1];
    const float* xLx      = (const float*)d_in[3];
    const float* W1 = (const float*)d_in[4];  const float* b1 = (const float*)d_in[5];
    const float* W2 = (const float*)d_in[6];  const float* b2 = (const float*)d_in[7];
    const float* chebW = (const float*)d_in[8]; const float* chebb = (const float*)d_in[9];
    const float* W3 = (const float*)d_in[10]; const float* b3 = (const float*)d_in[11];
    const float* W4 = (const float*)d_in[12]; const float* b4 = (const float*)d_in[13];
    const float* W5 = (const float*)d_in[14]; const float* b5 = (const float*)d_in[15];
    const float* W6 = (const float*)d_in[16]; const float* b6 = (const float*)d_in[17];
    const float* W8 = (const float*)d_in[18]; const float* b8 = (const float*)d_in[19];
    const float* W9 = (const float*)d_in[20]; const float* b9 = (const float*)d_in[21];
    const float* W7 = (const float*)d_in[22]; const float* b7 = (const float*)d_in[23];
    const float* gamma = (const float*)d_in[24]; const float* beta = (const float*)d_in[25];
    float* out = (float*)d_out;

    int n = in_sizes[0] / F_DIM;   // 100000
    int e = in_sizes[1] / 2;       // 600000
    int g = in_sizes[3] / F_DIM;   // 1000
    int npg = n / g;               // 100

    int pool_smem = (npg * 256 + 256 + npg) * 4;

    static cudaStream_t sB = nullptr;
    static cudaEvent_t evFork = nullptr, evGraphReady = nullptr, evSideDone = nullptr;
    static bool init_done = false;
    if (!init_done) {
        cudaFuncSetAttribute(gemm_bf16x3, cudaFuncAttributeMaxDynamicSharedMemorySize, GEMM_SMEM);
        cudaFuncSetAttribute(gemm12, cudaFuncAttributeMaxDynamicSharedMemorySize, GEMM12_SMEM);
        cudaFuncSetAttribute(pool_kernel, cudaFuncAttributeMaxDynamicSharedMemorySize, 112 * 1024);
        cudaStreamCreateWithFlags(&sB, cudaStreamNonBlocking);
        cudaEventCreateWithFlags(&evFork, cudaEventDisableTiming);
        cudaEventCreateWithFlags(&evGraphReady, cudaEventDisableTiming);
        cudaEventCreateWithFlags(&evSideDone, cudaEventDisableTiming);
        init_done = true;
    }

    bf16 *TxH = sym<bf16>(&d_TxH), *TxL = sym<bf16>(&d_TxL);
    bf16 *H3H = sym<bf16>(&d_H3H), *H3L = sym<bf16>(&d_H3L);
    float* H4 = sym<float>(&d_H4);
    float *deg = sym<float>(&d_deg), *ew = sym<float>(&d_ew);
    int *cnt = sym<int>(&d_cnt), *elist = sym<int>(&d_elist);
    float *T2 = sym<float>(&d_T2), *X2 = sym<float>(&d_X2);
    float *hc = sym<float>(&d_hc), *mu = sym<float>(&d_mu), *rstd = sym<float>(&d_rstd);
    bf16 *W1tH = sym<bf16>(&d_W1tH), *W1tL = sym<bf16>(&d_W1tL);
    bf16 *W2tH = sym<bf16>(&d_W2tH), *W2tL = sym<bf16>(&d_W2tL);
    bf16 *WcH = sym<bf16>(&d_WcH), *WcL = sym<bf16>(&d_WcL);
    bf16 *W4tH = sym<bf16>(&d_W4tH), *W4tL = sym<bf16>(&d_W4tL);
    bf16 *Wc2H = sym<bf16>(&d_Wc2H), *Wc2L = sym<bf16>(&d_Wc2L);
    bf16 *W8tH = sym<bf16>(&d_W8tH), *W8tL = sym<bf16>(&d_W8tL);
    bf16 *W9tH = sym<bf16>(&d_W9tH), *W9tL = sym<bf16>(&d_W9tL);
    float *b3c = sym<float>(&d_b3c), *bx = sym<float>(&d_bx);
    bf16 *xLxH = sym<bf16>(&d_xLxH), *xLxL = sym<bf16>(&d_xLxL);
    bf16 *T1H = sym<bf16>(&d_T1H), *T1L = sym<bf16>(&d_T1L);

    const int* src = edge;
    const int* dst = edge + e;

    // ---- fork side stream from main (legacy) stream ----
    cudaEventRecord(evFork, 0);
    cudaStreamWaitEvent(sB, evFork, 0);

    // ---- side chain (stream sB): topology first, then weights, then graph MLPs ----
    zero_dc<<<(n + 255) / 256, 256, 0, sB>>>(deg, cnt, n);
    build_graph<<<(e + 255) / 256, 256, 0, sB>>>(src, dst, e, deg, cnt, elist);
    ew_kernel<<<(e + 255) / 256, 256, 0, sB>>>(src, dst, deg, ew, e);
    cudaEventRecord(evGraphReady, sB);     // ew/elist/cnt ready (gates props)
    split_contig<<<(g * 128 + 255) / 256, 256, 0, sB>>>(xLx, xLxH, xLxL, g * 128);
    transpose3<<<640, 256, 0, sB>>>(W4, W4tH, W4tL, W8, W8tH, W8tL, W9, W9tH, W9tL);
    build_wcombo<<<385, 256, 0, sB>>>(chebW, W3, chebb, b3, WcH, WcL, b3c);
    build_wc2<<<129, 256, 0, sB>>>(W5, W6, b5, b6, Wc2H, Wc2L, bx);
    launch_gemm_s(sB, xLxH, xLxL, 128, W8tH, W8tL, 128, b8,
                  nullptr, 0, T1H, T1L, 256, g, 256, 128, 1);
    launch_gemm_s(sB, T1H, T1L, 256, W9tH, W9tL, 256, b9,
                  T2, 256, nullptr, nullptr, 0, g, 256, 256, 1);
    launch_gemm_s(sB, xLxH, xLxL, 128, Wc2H, Wc2L, 128, bx,
                  X2, 256, nullptr, nullptr, 0, g, 256, 128, 1);
    cudaEventRecord(evSideDone, sB);       // T2, X2 ready (gates pool)

    // ---- main chain (stream 0) ----
    transpose_w12<<<128, 256>>>(W1, W1tH, W1tL, W2, W2tH, W2tL);
    gemm12<<<(n + 127) / 128, 256, GEMM12_SMEM>>>(features, W1tH, W1tL, b1,
                                                  W2tH, W2tL, b2, TxH, TxL, n);

    cudaStreamWaitEvent(0, evGraphReady, 0);
    prop_split1<<<(n * 32 + 255) / 256, 256>>>(TxH, TxL, ew, src, elist, cnt, n);
    prop_split2<<<(n * 32 + 255) / 256, 256>>>(TxH, TxL, ew, src, elist, cnt, n);

    launch_gemm_s(0, TxH, TxL, 384, WcH, WcL, 384, b3c,
                  nullptr, 0, H3H, H3L, 256, n, 256, 384, 1);
    launch_gemm_s(0, H3H, H3L, 256, W4tH, W4tL, 256, b4,
                  H4, 256, nullptr, nullptr, 0, n, 256, 256, 1);

    cudaStreamWaitEvent(0, evSideDone, 0);
    pool_kernel<<<g, 256, pool_smem>>>(H4, T2, X2, hc, npg);
    bn_stats<<<C2, 256>>>(hc, mu, rstd, g);
    bn_final<<<g, 256>>>(hc, mu, rstd, gamma, beta, W7, b7, out);
}